// round 14
// baseline (speedup 1.0000x reference)
#include <cuda_runtime.h>
#include <cuda_fp16.h>
#include <mma.h>
using namespace nvcuda;

#define N_CLI 100000
#define N_AGG 1000
#define NE    1600000
#define D     128
#define NLAY  3

#define GEMM_SMEM ((64 * 136 + 128 * 136) * 2)   // 52224 B

// ---------------- scratch ----------------
__device__ float  g_xa0[N_AGG * D];
__device__ float  g_xa1[N_AGG * D];
__device__ __half g_Y16[2][N_AGG * D];
__device__ __half g_xc16a[N_CLI * D];
__device__ __half g_xc16b[N_CLI * D];
__device__ __half g_W16[NLAY * D * D];
__device__ float  g_Z[(N_CLI + 128) * D];
__device__ float  g_G0[N_CLI * D];
__device__ float  g_G1[N_CLI * D];
__device__ float  g_mean_a[N_AGG * D];
__device__ int    g_csr_c2a[NE];
__device__ int    g_csr_a2c[NE];
__device__ int    g_off_c2a[N_AGG + 1];
__device__ int    g_off_a2c[N_CLI + 1];
__device__ int    g_cur_c2a[N_AGG];
__device__ int    g_cur_a2c[N_CLI];
__device__ int    g_cnt_c2a[N_AGG];
__device__ int    g_cnt_a2c[N_CLI];
__device__ int    g_part[128];
__device__ float  g_invc_a[N_AGG];
__device__ float  g_invc_c[N_CLI];

// ---------------- CSR construction ----------------
__global__ void zero_int_kernel(int* p, int n) {
    int i = blockIdx.x * blockDim.x + threadIdx.x;
    if (i < n) p[i] = 0;
}

__global__ void hist_c2a_kernel(const int* __restrict__ dst, int* __restrict__ cnt) {
    __shared__ int h[N_AGG];
    for (int i = threadIdx.x; i < N_AGG; i += blockDim.x) h[i] = 0;
    __syncthreads();
    for (int e = blockIdx.x * blockDim.x + threadIdx.x; e < NE; e += gridDim.x * blockDim.x)
        atomicAdd(&h[dst[e]], 1);
    __syncthreads();
    for (int i = threadIdx.x; i < N_AGG; i += blockDim.x)
        if (h[i]) atomicAdd(&cnt[i], h[i]);
}

__global__ void hist_a2c_kernel(const int* __restrict__ dst, int* __restrict__ cnt) {
    int e = blockIdx.x * blockDim.x + threadIdx.x;
    if (e < NE) atomicAdd(&cnt[dst[e]], 1);
}

__global__ void scan_init_kernel(const int* __restrict__ cnt, int* __restrict__ off,
                                 int* __restrict__ cur, float* __restrict__ invc, int n) {
    __shared__ int wsum[32];
    __shared__ int carry;
    int tid = threadIdx.x, lane = tid & 31, wid = tid >> 5;
    if (tid == 0) carry = 0;
    __syncthreads();
    for (int base = 0; base < n; base += 1024) {
        int i = base + tid;
        int v = (i < n) ? cnt[i] : 0;
        int x = v;
        #pragma unroll
        for (int o = 1; o < 32; o <<= 1) {
            int t = __shfl_up_sync(0xffffffffu, x, o);
            if (lane >= o) x += t;
        }
        if (lane == 31) wsum[wid] = x;
        __syncthreads();
        if (wid == 0) {
            int s = wsum[lane];
            #pragma unroll
            for (int o = 1; o < 32; o <<= 1) {
                int t = __shfl_up_sync(0xffffffffu, s, o);
                if (lane >= o) s += t;
            }
            wsum[lane] = s;
        }
        __syncthreads();
        int excl = x - v + (wid ? wsum[wid - 1] : 0) + carry;
        if (i < n) {
            off[i] = excl;
            cur[i] = excl;
            invc[i] = 1.0f / fmaxf((float)v, 1.0f);
        }
        __syncthreads();
        if (tid == 0) carry += wsum[31];
        __syncthreads();
    }
    if (threadIdx.x == 0) off[n] = carry;
}

__global__ void scan_blocks_kernel(const int* __restrict__ cnt, int* __restrict__ off,
                                   int* __restrict__ part, int n) {
    __shared__ int wsum[32];
    int tid = threadIdx.x, lane = tid & 31, wid = tid >> 5;
    int i = blockIdx.x * 1024 + tid;
    int v = (i < n) ? cnt[i] : 0;
    int x = v;
    #pragma unroll
    for (int o = 1; o < 32; o <<= 1) {
        int t = __shfl_up_sync(0xffffffffu, x, o);
        if (lane >= o) x += t;
    }
    if (lane == 31) wsum[wid] = x;
    __syncthreads();
    if (wid == 0) {
        int s = wsum[lane];
        #pragma unroll
        for (int o = 1; o < 32; o <<= 1) {
            int t = __shfl_up_sync(0xffffffffu, s, o);
            if (lane >= o) s += t;
        }
        wsum[lane] = s;
    }
    __syncthreads();
    int excl = x - v + (wid ? wsum[wid - 1] : 0);
    if (i < n) off[i] = excl;
    if (tid == 1023) part[blockIdx.x] = excl + v;
}

__global__ void scan_part_kernel(int* part, int nb) {
    if (threadIdx.x == 0) {
        int acc = 0;
        for (int b = 0; b < nb; b++) {
            int v = part[b];
            part[b] = acc;
            acc += v;
        }
        part[nb] = acc;
    }
}

__global__ void scan_add_kernel(const int* __restrict__ cnt, int* __restrict__ off,
                                const int* __restrict__ part, int* __restrict__ cur,
                                float* __restrict__ invc, int n, int nb) {
    int i = blockIdx.x * blockDim.x + threadIdx.x;
    if (i < n) {
        int o = off[i] + part[i >> 10];
        off[i] = o;
        cur[i] = o;
        invc[i] = 1.0f / fmaxf((float)cnt[i], 1.0f);
    }
    if (i == 0) off[n] = part[nb];
}

__global__ void scatter_kernel(const int* __restrict__ src, const int* __restrict__ dst,
                               int* __restrict__ cur, int* __restrict__ csr) {
    int e = blockIdx.x * blockDim.x + threadIdx.x;
    if (e < NE) {
        int p = atomicAdd(&cur[dst[e]], 1);
        csr[p] = src[e];
    }
}

// ---------------- fp32 -> fp16 ----------------
__global__ void f2h_kernel(const float* __restrict__ x, __half* __restrict__ y, int n4) {
    int i = blockIdx.x * blockDim.x + threadIdx.x;
    if (i < n4) {
        float4 v = ((const float4*)x)[i];
        __half2 h0 = __floats2half2_rn(v.x, v.y);
        __half2 h1 = __floats2half2_rn(v.z, v.w);
        float2 pk;
        *(__half2*)&pk.x = h0;
        *(__half2*)&pk.y = h1;
        ((float2*)y)[i] = pk;
    }
}

// ---------------- tiny GEMM: Y16 = xa @ Wl ----------------
__global__ void gemm_small_h_kernel(const float* __restrict__ A, const float* __restrict__ W,
                                    __half* __restrict__ C) {
    __shared__ float row[D];
    int r = blockIdx.x, j = threadIdx.x;
    row[j] = A[r * D + j];
    __syncthreads();
    float acc = 0.f;
    #pragma unroll 8
    for (int k = 0; k < D; k++) acc += row[k] * W[k * D + j];
    C[r * D + j] = __float2half(acc);
}

// xa_new = leaky(mean @ Wl + xa @ Wr + b)
__global__ void agg_update_kernel(const float* __restrict__ mean, const float* __restrict__ xa,
                                  const float* __restrict__ Wl, const float* __restrict__ Wr,
                                  const float* __restrict__ b, float* __restrict__ out) {
    __shared__ float rm[D], rx[D];
    int r = blockIdx.x, j = threadIdx.x;
    rm[j] = mean[r * D + j];
    rx[j] = xa[r * D + j];
    __syncthreads();
    float acc = b[j];
    #pragma unroll 4
    for (int k = 0; k < D; k++) acc += rm[k] * Wl[k * D + j] + rx[k] * Wr[k * D + j];
    out[r * D + j] = (acc >= 0.f) ? acc : 0.1f * acc;
}

// ---------------- c2a aggregation: 512 thr = 8 edge-groups x 64 half2 lanes ----------------
__global__ void __launch_bounds__(512)
agg_c2a_h_kernel(const __half* __restrict__ xc16, const int* __restrict__ csr,
                 const int* __restrict__ off, const float* __restrict__ invc,
                 float* __restrict__ mean) {
    __shared__ float2 part[512];
    int a = blockIdx.x;
    int t = threadIdx.x;
    int c2 = t & 63;
    int g = t >> 6;
    int s = off[a], e = off[a + 1];
    const __half2* X2 = (const __half2*)xc16;
    float2 acc = make_float2(0.f, 0.f);
    int i = s + g;
    for (; i + 8 < e; i += 16) {
        int i0 = csr[i];
        int i1 = csr[i + 8];
        float2 f0 = __half22float2(X2[(size_t)i0 * 64 + c2]);
        float2 f1 = __half22float2(X2[(size_t)i1 * 64 + c2]);
        acc.x += f0.x + f1.x;
        acc.y += f0.y + f1.y;
    }
    if (i < e) {
        float2 f0 = __half22float2(X2[(size_t)csr[i] * 64 + c2]);
        acc.x += f0.x;
        acc.y += f0.y;
    }
    part[t] = acc;
    __syncthreads();
    if (g == 0) {
        float2 m = part[c2];
        #pragma unroll
        for (int k = 1; k < 8; k++) {
            float2 p = part[k * 64 + c2];
            m.x += p.x;
            m.y += p.y;
        }
        float ic = invc[a];
        ((float2*)mean)[a * 64 + c2] = make_float2(m.x * ic, m.y * ic);
    }
}

// ---------------- tensor-core GEMM (validated BM=64 variant) ----------------
__global__ void __launch_bounds__(256, 3)
gemm_h_kernel(const __half* __restrict__ A, const __half* __restrict__ W,
              float* __restrict__ Z, int M) {
    extern __shared__ __half sm[];
    __half* sA = sm;                // [64][136]
    __half* sW = sm + 64 * 136;     // [128][136]
    int tid = threadIdx.x;
    int r0 = blockIdx.x * 64;

    for (int i = tid; i < 64 * 16; i += 256) {
        int row = i >> 4, c8 = (i & 15) * 8;
        int rc = min(r0 + row, M - 1);
        *(float4*)(&sA[row * 136 + c8]) = *(const float4*)(A + (size_t)rc * D + c8);
    }
    for (int i = tid; i < 128 * 16; i += 256) {
        int row = i >> 4, c8 = (i & 15) * 8;
        *(float4*)(&sW[row * 136 + c8]) = *(const float4*)(W + row * D + c8);
    }
    __syncthreads();

    int warp = tid >> 5;
    int wm = warp >> 1;
    int wn = warp & 1;

    wmma::fragment<wmma::accumulator, 16, 16, 16, float> acc[4];
    #pragma unroll
    for (int j = 0; j < 4; j++) wmma::fill_fragment(acc[j], 0.f);

    #pragma unroll
    for (int k = 0; k < 128; k += 16) {
        wmma::fragment<wmma::matrix_a, 16, 16, 16, __half, wmma::row_major> af;
        wmma::load_matrix_sync(af, &sA[(wm * 16) * 136 + k], 136);
        #pragma unroll
        for (int j = 0; j < 4; j++) {
            wmma::fragment<wmma::matrix_b, 16, 16, 16, __half, wmma::row_major> bf;
            wmma::load_matrix_sync(bf, &sW[k * 136 + wn * 64 + j * 16], 136);
            wmma::mma_sync(acc[j], af, bf, acc[j]);
        }
    }

    #pragma unroll
    for (int j = 0; j < 4; j++)
        wmma::store_matrix_sync(&Z[(size_t)(r0 + wm * 16) * D + wn * 64 + j * 16],
                                acc[j], D, wmma::mem_row_major);
}

// ---------------- gather: G[c] = sum_{e in N(c)} Y16[csr[e]]  (R8 gather loop verbatim) ----------------
__global__ void gather_kernel(const __half* __restrict__ Y16,
                              const int* __restrict__ csr, const int* __restrict__ off,
                              float4* __restrict__ G) {
    int warp = (blockIdx.x * blockDim.x + threadIdx.x) >> 5;
    int lane = threadIdx.x & 31;
    if (warp >= N_CLI) return;
    int s = off[warp], e = off[warp + 1];
    const float2* Y2 = (const float2*)Y16;
    float4 acc = make_float4(0.f, 0.f, 0.f, 0.f);
    for (int base = s; base < e; base += 32) {
        int nv = min(32, e - base);
        int idx = (lane < nv) ? csr[base + lane] : 0;
        for (int t = 0; t < nv; t++) {
            int a = __shfl_sync(0xffffffffu, idx, t);
            float2 raw = Y2[a * 32 + lane];
            __half2 h0 = *(__half2*)&raw.x;
            __half2 h1 = *(__half2*)&raw.y;
            float2 f0 = __half22float2(h0);
            float2 f1 = __half22float2(h1);
            acc.x += f0.x; acc.y += f0.y; acc.z += f1.x; acc.w += f1.y;
        }
    }
    G[warp * 32 + lane] = acc;
}

// ---------------- combine: xc16 = leaky(Z + b + G*invc); LAST -> dot W_lin ----------------
template<bool LAST>
__global__ void combine_kernel(const float* __restrict__ Z, const float* __restrict__ bias,
                               const float4* __restrict__ G, const float* __restrict__ invc,
                               __half* __restrict__ xc16,
                               const float* __restrict__ Wlin, const float* __restrict__ blin,
                               float* __restrict__ outv) {
    __shared__ float sb[D];
    if (threadIdx.x < D) sb[threadIdx.x] = bias[threadIdx.x];
    __syncthreads();
    int warp = (blockIdx.x * blockDim.x + threadIdx.x) >> 5;
    int lane = threadIdx.x & 31;
    if (warp >= N_CLI) return;
    float ic = invc[warp];
    float4 acc = G[warp * 32 + lane];
    float4 z = ((const float4*)Z)[warp * 32 + lane];
    float4 b4 = *(const float4*)(&sb[lane * 4]);
    float4 v;
    v.x = z.x + b4.x + acc.x * ic;
    v.y = z.y + b4.y + acc.y * ic;
    v.z = z.z + b4.z + acc.z * ic;
    v.w = z.w + b4.w + acc.w * ic;
    v.x = (v.x >= 0.f) ? v.x : 0.1f * v.x;
    v.y = (v.y >= 0.f) ? v.y : 0.1f * v.y;
    v.z = (v.z >= 0.f) ? v.z : 0.1f * v.z;
    v.w = (v.w >= 0.f) ? v.w : 0.1f * v.w;
    if (LAST) {
        float4 w4 = ((const float4*)Wlin)[lane];
        float p = v.x * w4.x + v.y * w4.y + v.z * w4.z + v.w * w4.w;
        #pragma unroll
        for (int o = 16; o; o >>= 1) p += __shfl_xor_sync(0xffffffffu, p, o);
        if (lane == 0) outv[warp] = p + blin[0];
    } else {
        __half2 h0 = __floats2half2_rn(v.x, v.y);
        __half2 h1 = __floats2half2_rn(v.z, v.w);
        float2 pk;
        *(__half2*)&pk.x = h0;
        *(__half2*)&pk.y = h1;
        ((float2*)xc16)[warp * 32 + lane] = pk;
    }
}

// ---------------- launch: triple-stream with gather/gemm overlap ----------------
extern "C" void kernel_launch(void* const* d_in, const int* in_sizes, int n_in,
                              void* d_out, int out_size) {
    (void)in_sizes; (void)n_in; (void)out_size;
    const float* x_clients = (const float*)d_in[0];
    const float* x_agg     = (const float*)d_in[1];
    const int*   c2a_src   = (const int*)d_in[2];
    const int*   c2a_dst   = (const int*)d_in[3];
    const int*   a2c_src   = (const int*)d_in[4];
    const int*   a2c_dst   = (const int*)d_in[5];
    const float* Wl_c2a    = (const float*)d_in[6];
    const float* Wr_c2a    = (const float*)d_in[7];
    const float* b_c2a     = (const float*)d_in[8];
    const float* Wl_a2c    = (const float*)d_in[9];
    const float* Wr_a2c    = (const float*)d_in[10];
    const float* b_a2c     = (const float*)d_in[11];
    const float* W_lin     = (const float*)d_in[12];
    const float* b_lin     = (const float*)d_in[13];
    float* out = (float*)d_out;

    void *p_xa0, *p_xa1, *p_Y16, *p_xc16a, *p_xc16b, *p_W16, *p_Z, *p_G0, *p_G1, *p_mean;
    void *p_csr_c2a, *p_csr_a2c, *p_off_c2a, *p_off_a2c;
    void *p_cur_c2a, *p_cur_a2c, *p_cnt_c2a, *p_cnt_a2c, *p_part, *p_invc_a, *p_invc_c;
    cudaGetSymbolAddress(&p_xa0, g_xa0);
    cudaGetSymbolAddress(&p_xa1, g_xa1);
    cudaGetSymbolAddress(&p_Y16, g_Y16);
    cudaGetSymbolAddress(&p_xc16a, g_xc16a);
    cudaGetSymbolAddress(&p_xc16b, g_xc16b);
    cudaGetSymbolAddress(&p_W16, g_W16);
    cudaGetSymbolAddress(&p_Z, g_Z);
    cudaGetSymbolAddress(&p_G0, g_G0);
    cudaGetSymbolAddress(&p_G1, g_G1);
    cudaGetSymbolAddress(&p_mean, g_mean_a);
    cudaGetSymbolAddress(&p_csr_c2a, g_csr_c2a);
    cudaGetSymbolAddress(&p_csr_a2c, g_csr_a2c);
    cudaGetSymbolAddress(&p_off_c2a, g_off_c2a);
    cudaGetSymbolAddress(&p_off_a2c, g_off_a2c);
    cudaGetSymbolAddress(&p_cur_c2a, g_cur_c2a);
    cudaGetSymbolAddress(&p_cur_a2c, g_cur_a2c);
    cudaGetSymbolAddress(&p_cnt_c2a, g_cnt_c2a);
    cudaGetSymbolAddress(&p_cnt_a2c, g_cnt_a2c);
    cudaGetSymbolAddress(&p_part, g_part);
    cudaGetSymbolAddress(&p_invc_a, g_invc_a);
    cudaGetSymbolAddress(&p_invc_c, g_invc_c);

    cudaFuncSetAttribute(gemm_h_kernel, cudaFuncAttributeMaxDynamicSharedMemorySize, GEMM_SMEM);

    static cudaStream_t s1 = nullptr, s2 = nullptr;
    static cudaEvent_t evFork, evY0, evPrep, evCsr2, evCsrA, evXcL0, evXcL1,
                       evAgg0, evAgg1, evG1, evG2;
    if (!s1) {
        cudaStreamCreateWithFlags(&s1, cudaStreamNonBlocking);
        cudaStreamCreateWithFlags(&s2, cudaStreamNonBlocking);
        cudaEventCreateWithFlags(&evFork, cudaEventDisableTiming);
        cudaEventCreateWithFlags(&evY0,   cudaEventDisableTiming);
        cudaEventCreateWithFlags(&evPrep, cudaEventDisableTiming);
        cudaEventCreateWithFlags(&evCsr2, cudaEventDisableTiming);
        cudaEventCreateWithFlags(&evCsrA, cudaEventDisableTiming);
        cudaEventCreateWithFlags(&evXcL0, cudaEventDisableTiming);
        cudaEventCreateWithFlags(&evXcL1, cudaEventDisableTiming);
        cudaEventCreateWithFlags(&evAgg0, cudaEventDisableTiming);
        cudaEventCreateWithFlags(&evAgg1, cudaEventDisableTiming);
        cudaEventCreateWithFlags(&evG1,   cudaEventDisableTiming);
        cudaEventCreateWithFlags(&evG2,   cudaEventDisableTiming);
    }

    __half* Y16b[2] = {(__half*)p_Y16, (__half*)p_Y16 + N_AGG * D};
    __half* W16 = (__half*)p_W16;

    int grid_gemm = (N_CLI + 63) / 64;
    int grid_cu = (N_CLI * 32 + 255) / 256;
    int grid_e = (NE + 255) / 256;

    // ---- fork ----
    cudaEventRecord(evFork, 0);
    cudaStreamWaitEvent(s1, evFork, 0);
    cudaStreamWaitEvent(s2, evFork, 0);

    // ---- s1: prep chain ----
    f2h_kernel<<<(NLAY * D * D / 4 + 255) / 256, 256, 0, s1>>>(Wr_a2c, W16, NLAY * D * D / 4);
    f2h_kernel<<<(N_CLI * 32 + 255) / 256, 256, 0, s1>>>(x_clients, (__half*)p_xc16a, N_CLI * 32);
    gemm_small_h_kernel<<<N_AGG, 128, 0, s1>>>(x_agg, Wl_a2c, Y16b[0]);
    cudaEventRecord(evY0, s1);      // Y16[0] ready (gather0 dependency)
    gemm_h_kernel<<<grid_gemm, 256, GEMM_SMEM, s1>>>((const __half*)p_xc16a, W16,
                                                     (float*)p_Z, N_CLI);
    cudaEventRecord(evPrep, s1);    // Z(L0) ready

    // ---- s2: c2a CSR build ----
    zero_int_kernel<<<(N_AGG + 255) / 256, 256, 0, s2>>>((int*)p_cnt_c2a, N_AGG);
    hist_c2a_kernel<<<296, 256, 0, s2>>>(c2a_dst, (int*)p_cnt_c2a);
    scan_init_kernel<<<1, 1024, 0, s2>>>((const int*)p_cnt_c2a, (int*)p_off_c2a,
                                         (int*)p_cur_c2a, (float*)p_invc_a, N_AGG);
    scatter_kernel<<<grid_e, 256, 0, s2>>>(c2a_src, c2a_dst, (int*)p_cur_c2a, (int*)p_csr_c2a);
    cudaEventRecord(evCsr2, s2);

    // ---- main: a2c CSR build ----
    zero_int_kernel<<<(N_CLI + 255) / 256, 256>>>((int*)p_cnt_a2c, N_CLI);
    hist_a2c_kernel<<<grid_e, 256>>>(a2c_dst, (int*)p_cnt_a2c);
    int nb = (N_CLI + 1023) / 1024;
    scan_blocks_kernel<<<nb, 1024>>>((const int*)p_cnt_a2c, (int*)p_off_a2c, (int*)p_part, N_CLI);
    scan_part_kernel<<<1, 32>>>((int*)p_part, nb);
    scan_add_kernel<<<(N_CLI + 255) / 256, 256>>>((const int*)p_cnt_a2c, (int*)p_off_a2c,
                                                  (const int*)p_part, (int*)p_cur_a2c,
                                                  (float*)p_invc_c, N_CLI, nb);
    scatter_kernel<<<grid_e, 256>>>(a2c_src, a2c_dst, (int*)p_cur_a2c, (int*)p_csr_a2c);
    cudaEventRecord(evCsrA, 0);

    // ---- layer 0 (main): gather0 (needs Y16[0] + a2c CSR), then combine0 (needs Z) ----
    cudaStreamWaitEvent(0, evY0, 0);
    gather_kernel<<<grid_cu, 256>>>(Y16b[0], (const int*)p_csr_a2c, (const int*)p_off_a2c,
                                    (float4*)p_G0);
    cudaStreamWaitEvent(0, evPrep, 0);
    combine_kernel<false><<<grid_cu, 256>>>(
        (const float*)p_Z, b_a2c, (const float4*)p_G0, (const float*)p_invc_c,
        (__half*)p_xc16b, W_lin, b_lin, out);
    cudaEventRecord(evXcL0, 0);     // xc16b ready; Y16[0], Z, G0 free

    // ---- s1: L0 c2a chain (needs c2a CSR; reads xc16a in-stream) ----
    cudaStreamWaitEvent(s1, evCsr2, 0);
    agg_c2a_h_kernel<<<N_AGG, 512, 0, s1>>>((const __half*)p_xc16a, (const int*)p_csr_c2a,
                                            (const int*)p_off_c2a, (const float*)p_invc_a,
                                            (float*)p_mean);
    agg_update_kernel<<<N_AGG, 128, 0, s1>>>((const float*)p_mean, x_agg,
                                             Wl_c2a, Wr_c2a, b_c2a, (float*)p_xa0);
    gemm_small_h_kernel<<<N_AGG, 128, 0, s1>>>((const float*)p_xa0, Wl_a2c + 1 * D * D, Y16b[1]);
    cudaEventRecord(evAgg0, s1);    // Y16[1] ready; xc16a reader done

    // ---- s1: L1 c2a chain (reads xc16b, writes Y16[0]) ----
    cudaStreamWaitEvent(s1, evXcL0, 0);
    agg_c2a_h_kernel<<<N_AGG, 512, 0, s1>>>((const __half*)p_xc16b, (const int*)p_csr_c2a,
                                            (const int*)p_off_c2a, (const float*)p_invc_a,
                                            (float*)p_mean);
    agg_update_kernel<<<N_AGG, 128, 0, s1>>>((const float*)p_mean, (const float*)p_xa0,
                                             Wl_c2a + 1 * D * D, Wr_c2a + 1 * D * D,
                                             b_c2a + 1 * D, (float*)p_xa1);
    gemm_small_h_kernel<<<N_AGG, 128, 0, s1>>>((const float*)p_xa1, Wl_a2c + 2 * D * D, Y16b[0]);
    cudaEventRecord(evAgg1, s1);    // Y16[0] (L2 msg) ready

    // ---- s2: gather1 (needs Y16[1] + a2c CSR), writes G1 ----
    cudaStreamWaitEvent(s2, evAgg0, 0);
    cudaStreamWaitEvent(s2, evCsrA, 0);
    gather_kernel<<<grid_cu, 256, 0, s2>>>(Y16b[1], (const int*)p_csr_a2c,
                                           (const int*)p_off_a2c, (float4*)p_G1);
    cudaEventRecord(evG1, s2);

    // ---- layer 1 (main): gemm1 runs concurrent with gather1 ----
    gemm_h_kernel<<<grid_gemm, 256, GEMM_SMEM>>>((const __half*)p_xc16b, W16 + 1 * D * D,
                                                 (float*)p_Z, N_CLI);
    cudaStreamWaitEvent(0, evG1, 0);
    // combine1 writes xc16a; its reader (s1 L0 agg_c2a) finished before evAgg0 < evG1. Safe.
    combine_kernel<false><<<grid_cu, 256>>>(
        (const float*)p_Z, b_a2c + 1 * D, (const float4*)p_G1, (const float*)p_invc_c,
        (__half*)p_xc16a, W_lin, b_lin, out);
    cudaEventRecord(evXcL1, 0);

    // ---- s2: gather2 (needs Y16[0] from s1-L1 chain), writes G0 ----
    // G0's last reader (combine0) precedes evXcL0 < evAgg1. Safe.
    cudaStreamWaitEvent(s2, evAgg1, 0);
    gather_kernel<<<grid_cu, 256, 0, s2>>>(Y16b[0], (const int*)p_csr_a2c,
                                           (const int*)p_off_a2c, (float4*)p_G0);
    cudaEventRecord(evG2, s2);

    // ---- layer 2 (main): gemm2 concurrent with gather2 ----
    gemm_h_kernel<<<grid_gemm, 256, GEMM_SMEM>>>((const __half*)p_xc16a, W16 + 2 * D * D,
                                                 (float*)p_Z, N_CLI);
    cudaStreamWaitEvent(0, evG2, 0);
    combine_kernel<true><<<grid_cu, 256>>>(
        (const float*)p_Z, b_a2c + 2 * D, (const float4*)p_G0, (const float*)p_invc_c,
        (__half*)p_xc16b, W_lin, b_lin, out);
}

// round 15
// speedup vs baseline: 1.0472x; 1.0472x over previous
#include <cuda_runtime.h>
#include <cuda_fp16.h>
#include <mma.h>
using namespace nvcuda;

#define N_CLI 100000
#define N_AGG 1000
#define NE    1600000
#define D     128
#define NLAY  3

#define GEMM_SMEM ((64 * 136 + 128 * 136) * 2)   // 52224 B
#define RSPLIT    50048                            // 782 blocks * 64 rows

// ---------------- scratch ----------------
__device__ float  g_xa0[N_AGG * D];
__device__ float  g_xa1[N_AGG * D];
__device__ __half g_Y16[2][N_AGG * D];
__device__ __half g_xc16a[N_CLI * D];
__device__ __half g_xc16b[N_CLI * D];
__device__ __half g_W16[NLAY * D * D];
__device__ float  g_Z[(N_CLI + 128) * D];
__device__ float  g_mean_a[N_AGG * D];
__device__ int    g_csr_c2a[NE];
__device__ int    g_csr_a2c[NE];
__device__ int    g_off_c2a[N_AGG + 1];
__device__ int    g_off_a2c[N_CLI + 1];
__device__ int    g_cur_c2a[N_AGG];
__device__ int    g_cur_a2c[N_CLI];
__device__ int    g_cnt_c2a[N_AGG];
__device__ int    g_cnt_a2c[N_CLI];
__device__ int    g_part[128];
__device__ float  g_invc_a[N_AGG];
__device__ float  g_invc_c[N_CLI];

// ---------------- CSR construction ----------------
__global__ void zero_int_kernel(int* p, int n) {
    int i = blockIdx.x * blockDim.x + threadIdx.x;
    if (i < n) p[i] = 0;
}

__global__ void hist_c2a_kernel(const int* __restrict__ dst, int* __restrict__ cnt) {
    __shared__ int h[N_AGG];
    for (int i = threadIdx.x; i < N_AGG; i += blockDim.x) h[i] = 0;
    __syncthreads();
    for (int e = blockIdx.x * blockDim.x + threadIdx.x; e < NE; e += gridDim.x * blockDim.x)
        atomicAdd(&h[dst[e]], 1);
    __syncthreads();
    for (int i = threadIdx.x; i < N_AGG; i += blockDim.x)
        if (h[i]) atomicAdd(&cnt[i], h[i]);
}

__global__ void hist_a2c_kernel(const int* __restrict__ dst, int* __restrict__ cnt) {
    int e = blockIdx.x * blockDim.x + threadIdx.x;
    if (e < NE) atomicAdd(&cnt[dst[e]], 1);
}

__global__ void scan_init_kernel(const int* __restrict__ cnt, int* __restrict__ off,
                                 int* __restrict__ cur, float* __restrict__ invc, int n) {
    __shared__ int wsum[32];
    __shared__ int carry;
    int tid = threadIdx.x, lane = tid & 31, wid = tid >> 5;
    if (tid == 0) carry = 0;
    __syncthreads();
    for (int base = 0; base < n; base += 1024) {
        int i = base + tid;
        int v = (i < n) ? cnt[i] : 0;
        int x = v;
        #pragma unroll
        for (int o = 1; o < 32; o <<= 1) {
            int t = __shfl_up_sync(0xffffffffu, x, o);
            if (lane >= o) x += t;
        }
        if (lane == 31) wsum[wid] = x;
        __syncthreads();
        if (wid == 0) {
            int s = wsum[lane];
            #pragma unroll
            for (int o = 1; o < 32; o <<= 1) {
                int t = __shfl_up_sync(0xffffffffu, s, o);
                if (lane >= o) s += t;
            }
            wsum[lane] = s;
        }
        __syncthreads();
        int excl = x - v + (wid ? wsum[wid - 1] : 0) + carry;
        if (i < n) {
            off[i] = excl;
            cur[i] = excl;
            invc[i] = 1.0f / fmaxf((float)v, 1.0f);
        }
        __syncthreads();
        if (tid == 0) carry += wsum[31];
        __syncthreads();
    }
    if (threadIdx.x == 0) off[n] = carry;
}

__global__ void scan_blocks_kernel(const int* __restrict__ cnt, int* __restrict__ off,
                                   int* __restrict__ part, int n) {
    __shared__ int wsum[32];
    int tid = threadIdx.x, lane = tid & 31, wid = tid >> 5;
    int i = blockIdx.x * 1024 + tid;
    int v = (i < n) ? cnt[i] : 0;
    int x = v;
    #pragma unroll
    for (int o = 1; o < 32; o <<= 1) {
        int t = __shfl_up_sync(0xffffffffu, x, o);
        if (lane >= o) x += t;
    }
    if (lane == 31) wsum[wid] = x;
    __syncthreads();
    if (wid == 0) {
        int s = wsum[lane];
        #pragma unroll
        for (int o = 1; o < 32; o <<= 1) {
            int t = __shfl_up_sync(0xffffffffu, s, o);
            if (lane >= o) s += t;
        }
        wsum[lane] = s;
    }
    __syncthreads();
    int excl = x - v + (wid ? wsum[wid - 1] : 0);
    if (i < n) off[i] = excl;
    if (tid == 1023) part[blockIdx.x] = excl + v;
}

__global__ void scan_part_kernel(int* part, int nb) {
    if (threadIdx.x == 0) {
        int acc = 0;
        for (int b = 0; b < nb; b++) {
            int v = part[b];
            part[b] = acc;
            acc += v;
        }
        part[nb] = acc;
    }
}

__global__ void scan_add_kernel(const int* __restrict__ cnt, int* __restrict__ off,
                                const int* __restrict__ part, int* __restrict__ cur,
                                float* __restrict__ invc, int n, int nb) {
    int i = blockIdx.x * blockDim.x + threadIdx.x;
    if (i < n) {
        int o = off[i] + part[i >> 10];
        off[i] = o;
        cur[i] = o;
        invc[i] = 1.0f / fmaxf((float)cnt[i], 1.0f);
    }
    if (i == 0) off[n] = part[nb];
}

__global__ void scatter_kernel(const int* __restrict__ src, const int* __restrict__ dst,
                               int* __restrict__ cur, int* __restrict__ csr) {
    int e = blockIdx.x * blockDim.x + threadIdx.x;
    if (e < NE) {
        int p = atomicAdd(&cur[dst[e]], 1);
        csr[p] = src[e];
    }
}

// ---------------- fp32 -> fp16 ----------------
__global__ void f2h_kernel(const float* __restrict__ x, __half* __restrict__ y, int n4) {
    int i = blockIdx.x * blockDim.x + threadIdx.x;
    if (i < n4) {
        float4 v = ((const float4*)x)[i];
        __half2 h0 = __floats2half2_rn(v.x, v.y);
        __half2 h1 = __floats2half2_rn(v.z, v.w);
        float2 pk;
        *(__half2*)&pk.x = h0;
        *(__half2*)&pk.y = h1;
        ((float2*)y)[i] = pk;
    }
}

// ---------------- tiny GEMM: Y16 = xa @ Wl ----------------
__global__ void gemm_small_h_kernel(const float* __restrict__ A, const float* __restrict__ W,
                                    __half* __restrict__ C) {
    __shared__ float row[D];
    int r = blockIdx.x, j = threadIdx.x;
    row[j] = A[r * D + j];
    __syncthreads();
    float acc = 0.f;
    #pragma unroll 8
    for (int k = 0; k < D; k++) acc += row[k] * W[k * D + j];
    C[r * D + j] = __float2half(acc);
}

// xa_new = leaky(mean @ Wl + xa @ Wr + b)
__global__ void agg_update_kernel(const float* __restrict__ mean, const float* __restrict__ xa,
                                  const float* __restrict__ Wl, const float* __restrict__ Wr,
                                  const float* __restrict__ b, float* __restrict__ out) {
    __shared__ float rm[D], rx[D];
    int r = blockIdx.x, j = threadIdx.x;
    rm[j] = mean[r * D + j];
    rx[j] = xa[r * D + j];
    __syncthreads();
    float acc = b[j];
    #pragma unroll 4
    for (int k = 0; k < D; k++) acc += rm[k] * Wl[k * D + j] + rx[k] * Wr[k * D + j];
    out[r * D + j] = (acc >= 0.f) ? acc : 0.1f * acc;
}

// ---------------- c2a aggregation: 512 thr = 8 edge-groups x 64 half2 lanes ----------------
__global__ void __launch_bounds__(512)
agg_c2a_h_kernel(const __half* __restrict__ xc16, const int* __restrict__ csr,
                 const int* __restrict__ off, const float* __restrict__ invc,
                 float* __restrict__ mean) {
    __shared__ float2 part[512];
    int a = blockIdx.x;
    int t = threadIdx.x;
    int c2 = t & 63;
    int g = t >> 6;
    int s = off[a], e = off[a + 1];
    const __half2* X2 = (const __half2*)xc16;
    float2 acc = make_float2(0.f, 0.f);
    int i = s + g;
    for (; i + 8 < e; i += 16) {
        int i0 = csr[i];
        int i1 = csr[i + 8];
        float2 f0 = __half22float2(X2[(size_t)i0 * 64 + c2]);
        float2 f1 = __half22float2(X2[(size_t)i1 * 64 + c2]);
        acc.x += f0.x + f1.x;
        acc.y += f0.y + f1.y;
    }
    if (i < e) {
        float2 f0 = __half22float2(X2[(size_t)csr[i] * 64 + c2]);
        acc.x += f0.x;
        acc.y += f0.y;
    }
    part[t] = acc;
    __syncthreads();
    if (g == 0) {
        float2 m = part[c2];
        #pragma unroll
        for (int k = 1; k < 8; k++) {
            float2 p = part[k * 64 + c2];
            m.x += p.x;
            m.y += p.y;
        }
        float ic = invc[a];
        ((float2*)mean)[a * 64 + c2] = make_float2(m.x * ic, m.y * ic);
    }
}

// ---------------- tensor-core GEMM (BM=64 body, + row base for split) ----------------
__global__ void __launch_bounds__(256, 3)
gemm_h_kernel(const __half* __restrict__ A, const __half* __restrict__ W,
              float* __restrict__ Z, int M, int base) {
    extern __shared__ __half sm[];
    __half* sA = sm;                // [64][136]
    __half* sW = sm + 64 * 136;     // [128][136]
    int tid = threadIdx.x;
    int r0 = base + blockIdx.x * 64;

    for (int i = tid; i < 64 * 16; i += 256) {
        int row = i >> 4, c8 = (i & 15) * 8;
        int rc = min(r0 + row, M - 1);
        *(float4*)(&sA[row * 136 + c8]) = *(const float4*)(A + (size_t)rc * D + c8);
    }
    for (int i = tid; i < 128 * 16; i += 256) {
        int row = i >> 4, c8 = (i & 15) * 8;
        *(float4*)(&sW[row * 136 + c8]) = *(const float4*)(W + row * D + c8);
    }
    __syncthreads();

    int warp = tid >> 5;
    int wm = warp >> 1;
    int wn = warp & 1;

    wmma::fragment<wmma::accumulator, 16, 16, 16, float> acc[4];
    #pragma unroll
    for (int j = 0; j < 4; j++) wmma::fill_fragment(acc[j], 0.f);

    #pragma unroll
    for (int k = 0; k < 128; k += 16) {
        wmma::fragment<wmma::matrix_a, 16, 16, 16, __half, wmma::row_major> af;
        wmma::load_matrix_sync(af, &sA[(wm * 16) * 136 + k], 136);
        #pragma unroll
        for (int j = 0; j < 4; j++) {
            wmma::fragment<wmma::matrix_b, 16, 16, 16, __half, wmma::row_major> bf;
            wmma::load_matrix_sync(bf, &sW[k * 136 + wn * 64 + j * 16], 136);
            wmma::mma_sync(acc[j], af, bf, acc[j]);
        }
    }

    #pragma unroll
    for (int j = 0; j < 4; j++)
        wmma::store_matrix_sync(&Z[(size_t)(r0 + wm * 16) * D + wn * 64 + j * 16],
                                acc[j], D, wmma::mem_row_major);
}

// ---------------- client update (R8 body, + row range for split) ----------------
template<bool LAST>
__global__ void client_update_h_kernel(const float* __restrict__ Z, const float* __restrict__ bias,
                                       const __half* __restrict__ Y16,
                                       const int* __restrict__ csr, const int* __restrict__ off,
                                       const float* __restrict__ invc,
                                       __half* __restrict__ xc16,
                                       const float* __restrict__ Wlin,
                                       const float* __restrict__ blin,
                                       float* __restrict__ outv, int base, int end) {
    __shared__ float sb[D];
    if (threadIdx.x < D) sb[threadIdx.x] = bias[threadIdx.x];
    __syncthreads();
    int warp = base + ((blockIdx.x * blockDim.x + threadIdx.x) >> 5);
    int lane = threadIdx.x & 31;
    if (warp >= end) return;
    int s = off[warp], e = off[warp + 1];
    const float2* Y2 = (const float2*)Y16;
    float4 acc = make_float4(0.f, 0.f, 0.f, 0.f);
    for (int bb = s; bb < e; bb += 32) {
        int nv = min(32, e - bb);
        int idx = (lane < nv) ? csr[bb + lane] : 0;
        for (int t = 0; t < nv; t++) {
            int a = __shfl_sync(0xffffffffu, idx, t);
            float2 raw = Y2[a * 32 + lane];
            __half2 h0 = *(__half2*)&raw.x;
            __half2 h1 = *(__half2*)&raw.y;
            float2 f0 = __half22float2(h0);
            float2 f1 = __half22float2(h1);
            acc.x += f0.x; acc.y += f0.y; acc.z += f1.x; acc.w += f1.y;
        }
    }
    float ic = invc[warp];
    float4 z = ((const float4*)Z)[(size_t)warp * 32 + lane];
    float4 b4 = *(const float4*)(&sb[lane * 4]);
    float4 v;
    v.x = z.x + b4.x + acc.x * ic;
    v.y = z.y + b4.y + acc.y * ic;
    v.z = z.z + b4.z + acc.z * ic;
    v.w = z.w + b4.w + acc.w * ic;
    v.x = (v.x >= 0.f) ? v.x : 0.1f * v.x;
    v.y = (v.y >= 0.f) ? v.y : 0.1f * v.y;
    v.z = (v.z >= 0.f) ? v.z : 0.1f * v.z;
    v.w = (v.w >= 0.f) ? v.w : 0.1f * v.w;
    if (LAST) {
        float4 w4 = ((const float4*)Wlin)[lane];
        float p = v.x * w4.x + v.y * w4.y + v.z * w4.z + v.w * w4.w;
        #pragma unroll
        for (int o = 16; o; o >>= 1) p += __shfl_xor_sync(0xffffffffu, p, o);
        if (lane == 0) outv[warp] = p + blin[0];
    } else {
        __half2 h0 = __floats2half2_rn(v.x, v.y);
        __half2 h1 = __floats2half2_rn(v.z, v.w);
        float2 pk;
        *(__half2*)&pk.x = h0;
        *(__half2*)&pk.y = h1;
        ((float2*)xc16)[(size_t)warp * 32 + lane] = pk;
    }
}

// ---------------- launch: triple-stream, split gemm/cu pipeline ----------------
extern "C" void kernel_launch(void* const* d_in, const int* in_sizes, int n_in,
                              void* d_out, int out_size) {
    (void)in_sizes; (void)n_in; (void)out_size;
    const float* x_clients = (const float*)d_in[0];
    const float* x_agg     = (const float*)d_in[1];
    const int*   c2a_src   = (const int*)d_in[2];
    const int*   c2a_dst   = (const int*)d_in[3];
    const int*   a2c_src   = (const int*)d_in[4];
    const int*   a2c_dst   = (const int*)d_in[5];
    const float* Wl_c2a    = (const float*)d_in[6];
    const float* Wr_c2a    = (const float*)d_in[7];
    const float* b_c2a     = (const float*)d_in[8];
    const float* Wl_a2c    = (const float*)d_in[9];
    const float* Wr_a2c    = (const float*)d_in[10];
    const float* b_a2c     = (const float*)d_in[11];
    const float* W_lin     = (const float*)d_in[12];
    const float* b_lin     = (const float*)d_in[13];
    float* out = (float*)d_out;

    void *p_xa0, *p_xa1, *p_Y16, *p_xc16a, *p_xc16b, *p_W16, *p_Z, *p_mean;
    void *p_csr_c2a, *p_csr_a2c, *p_off_c2a, *p_off_a2c;
    void *p_cur_c2a, *p_cur_a2c, *p_cnt_c2a, *p_cnt_a2c, *p_part, *p_invc_a, *p_invc_c;
    cudaGetSymbolAddress(&p_xa0, g_xa0);
    cudaGetSymbolAddress(&p_xa1, g_xa1);
    cudaGetSymbolAddress(&p_Y16, g_Y16);
    cudaGetSymbolAddress(&p_xc16a, g_xc16a);
    cudaGetSymbolAddress(&p_xc16b, g_xc16b);
    cudaGetSymbolAddress(&p_W16, g_W16);
    cudaGetSymbolAddress(&p_Z, g_Z);
    cudaGetSymbolAddress(&p_mean, g_mean_a);
    cudaGetSymbolAddress(&p_csr_c2a, g_csr_c2a);
    cudaGetSymbolAddress(&p_csr_a2c, g_csr_a2c);
    cudaGetSymbolAddress(&p_off_c2a, g_off_c2a);
    cudaGetSymbolAddress(&p_off_a2c, g_off_a2c);
    cudaGetSymbolAddress(&p_cur_c2a, g_cur_c2a);
    cudaGetSymbolAddress(&p_cur_a2c, g_cur_a2c);
    cudaGetSymbolAddress(&p_cnt_c2a, g_cnt_c2a);
    cudaGetSymbolAddress(&p_cnt_a2c, g_cnt_a2c);
    cudaGetSymbolAddress(&p_part, g_part);
    cudaGetSymbolAddress(&p_invc_a, g_invc_a);
    cudaGetSymbolAddress(&p_invc_c, g_invc_c);

    cudaFuncSetAttribute(gemm_h_kernel, cudaFuncAttributeMaxDynamicSharedMemorySize, GEMM_SMEM);

    static cudaStream_t s1 = nullptr, s2 = nullptr;
    static cudaEvent_t evFork, evPrep, evCsr2, evCsrA, evXcL0, evAgg0, evAgg1;
    static cudaEvent_t evZ1a, evCu1a, evZ2a, evCu2a;
    if (!s1) {
        cudaStreamCreateWithFlags(&s1, cudaStreamNonBlocking);
        cudaStreamCreateWithFlags(&s2, cudaStreamNonBlocking);
        cudaEventCreateWithFlags(&evFork, cudaEventDisableTiming);
        cudaEventCreateWithFlags(&evPrep, cudaEventDisableTiming);
        cudaEventCreateWithFlags(&evCsr2, cudaEventDisableTiming);
        cudaEventCreateWithFlags(&evCsrA, cudaEventDisableTiming);
        cudaEventCreateWithFlags(&evXcL0, cudaEventDisableTiming);
        cudaEventCreateWithFlags(&evAgg0, cudaEventDisableTiming);
        cudaEventCreateWithFlags(&evAgg1, cudaEventDisableTiming);
        cudaEventCreateWithFlags(&evZ1a, cudaEventDisableTiming);
        cudaEventCreateWithFlags(&evCu1a, cudaEventDisableTiming);
        cudaEventCreateWithFlags(&evZ2a, cudaEventDisableTiming);
        cudaEventCreateWithFlags(&evCu2a, cudaEventDisableTiming);
    }

    __half* Y16b[2] = {(__half*)p_Y16, (__half*)p_Y16 + N_AGG * D};
    __half* W16 = (__half*)p_W16;

    int grid_gemm = (N_CLI + 63) / 64;            // 1563
    int gA = RSPLIT / 64;                          // 782 blocks (rows [0, RSPLIT))
    int gB = grid_gemm - gA;                       // 781 blocks (rows [RSPLIT, ...))
    int grid_cu  = (N_CLI * 32 + 255) / 256;
    int cuA = (RSPLIT * 32 + 255) / 256;
    int cuB = ((N_CLI - RSPLIT) * 32 + 255) / 256;
    int grid_e = (NE + 255) / 256;

    // ---- fork ----
    cudaEventRecord(evFork, 0);
    cudaStreamWaitEvent(s1, evFork, 0);
    cudaStreamWaitEvent(s2, evFork, 0);

    // ---- s1: prep chain ----
    f2h_kernel<<<(NLAY * D * D / 4 + 255) / 256, 256, 0, s1>>>(Wr_a2c, W16, NLAY * D * D / 4);
    f2h_kernel<<<(N_CLI * 32 + 255) / 256, 256, 0, s1>>>(x_clients, (__half*)p_xc16a, N_CLI * 32);
    gemm_small_h_kernel<<<N_AGG, 128, 0, s1>>>(x_agg, Wl_a2c, Y16b[0]);
    gemm_h_kernel<<<grid_gemm, 256, GEMM_SMEM, s1>>>((const __half*)p_xc16a, W16,
                                                     (float*)p_Z, N_CLI, 0);
    cudaEventRecord(evPrep, s1);

    // ---- s2: c2a CSR build ----
    zero_int_kernel<<<(N_AGG + 255) / 256, 256, 0, s2>>>((int*)p_cnt_c2a, N_AGG);
    hist_c2a_kernel<<<296, 256, 0, s2>>>(c2a_dst, (int*)p_cnt_c2a);
    scan_init_kernel<<<1, 1024, 0, s2>>>((const int*)p_cnt_c2a, (int*)p_off_c2a,
                                         (int*)p_cur_c2a, (float*)p_invc_a, N_AGG);
    scatter_kernel<<<grid_e, 256, 0, s2>>>(c2a_src, c2a_dst, (int*)p_cur_c2a, (int*)p_csr_c2a);
    cudaEventRecord(evCsr2, s2);

    // ---- main: a2c CSR build ----
    zero_int_kernel<<<(N_CLI + 255) / 256, 256>>>((int*)p_cnt_a2c, N_CLI);
    hist_a2c_kernel<<<grid_e, 256>>>(a2c_dst, (int*)p_cnt_a2c);
    int nb = (N_CLI + 1023) / 1024;
    scan_blocks_kernel<<<nb, 1024>>>((const int*)p_cnt_a2c, (int*)p_off_a2c, (int*)p_part, N_CLI);
    scan_part_kernel<<<1, 32>>>((int*)p_part, nb);
    scan_add_kernel<<<(N_CLI + 255) / 256, 256>>>((const int*)p_cnt_a2c, (int*)p_off_a2c,
                                                  (const int*)p_part, (int*)p_cur_a2c,
                                                  (float*)p_invc_c, N_CLI, nb);
    scatter_kernel<<<grid_e, 256>>>(a2c_src, a2c_dst, (int*)p_cur_a2c, (int*)p_csr_a2c);
    cudaEventRecord(evCsrA, 0);

    // ---- layer 0 (main): full cu ----
    cudaStreamWaitEvent(0, evPrep, 0);
    client_update_h_kernel<false><<<grid_cu, 256>>>(
        (const float*)p_Z, b_a2c, Y16b[0], (const int*)p_csr_a2c,
        (const int*)p_off_a2c, (const float*)p_invc_c, (__half*)p_xc16b,
        W_lin, b_lin, out, 0, N_CLI);
    cudaEventRecord(evXcL0, 0);

    // ---- s1: L0 c2a chain ----
    cudaStreamWaitEvent(s1, evCsr2, 0);
    agg_c2a_h_kernel<<<N_AGG, 512, 0, s1>>>((const __half*)p_xc16a, (const int*)p_csr_c2a,
                                            (const int*)p_off_c2a, (const float*)p_invc_a,
                                            (float*)p_mean);
    agg_update_kernel<<<N_AGG, 128, 0, s1>>>((const float*)p_mean, x_agg,
                                             Wl_c2a, Wr_c2a, b_c2a, (float*)p_xa0);
    gemm_small_h_kernel<<<N_AGG, 128, 0, s1>>>((const float*)p_xa0, Wl_a2c + 1 * D * D, Y16b[1]);
    cudaEventRecord(evAgg0, s1);

    // ---- s1: L1 c2a chain ----
    cudaStreamWaitEvent(s1, evXcL0, 0);
    agg_c2a_h_kernel<<<N_AGG, 512, 0, s1>>>((const __half*)p_xc16b, (const int*)p_csr_c2a,
                                            (const int*)p_off_c2a, (const float*)p_invc_a,
                                            (float*)p_mean);
    agg_update_kernel<<<N_AGG, 128, 0, s1>>>((const float*)p_mean, (const float*)p_xa0,
                                             Wl_c2a + 1 * D * D, Wr_c2a + 1 * D * D,
                                             b_c2a + 1 * D, (float*)p_xa1);
    gemm_small_h_kernel<<<N_AGG, 128, 0, s1>>>((const float*)p_xa1, Wl_a2c + 2 * D * D, Y16b[0]);
    cudaEventRecord(evAgg1, s1);

    // ---- layer 1: split gemm/cu pipeline ----
    // main: gemm half A, then half B; s2: cu half A concurrent with gemm half B.
    gemm_h_kernel<<<gA, 256, GEMM_SMEM>>>((const __half*)p_xc16b, W16 + 1 * D * D,
                                          (float*)p_Z, N_CLI, 0);
    cudaEventRecord(evZ1a, 0);
    gemm_h_kernel<<<gB, 256, GEMM_SMEM>>>((const __half*)p_xc16b, W16 + 1 * D * D,
                                          (float*)p_Z, N_CLI, RSPLIT);
    // s2: cu half A (needs Z-halfA + Y16[1]; xc16a WAR covered: its reader done before evAgg0)
    cudaStreamWaitEvent(s2, evZ1a, 0);
    cudaStreamWaitEvent(s2, evAgg0, 0);
    client_update_h_kernel<false><<<cuA, 256, 0, s2>>>(
        (const float*)p_Z, b_a2c + 1 * D, Y16b[1], (const int*)p_csr_a2c,
        (const int*)p_off_a2c, (const float*)p_invc_c, (__half*)p_xc16a,
        W_lin, b_lin, out, 0, RSPLIT);
    cudaEventRecord(evCu1a, s2);
    // main: cu half B (Z-halfB in-stream; Y16[1] needs evAgg0)
    cudaStreamWaitEvent(0, evAgg0, 0);
    client_update_h_kernel<false><<<cuB, 256>>>(
        (const float*)p_Z, b_a2c + 1 * D, Y16b[1], (const int*)p_csr_a2c,
        (const int*)p_off_a2c, (const float*)p_invc_c, (__half*)p_xc16a,
        W_lin, b_lin, out, RSPLIT, N_CLI);
    cudaStreamWaitEvent(0, evCu1a, 0);   // full xc16a before gemm2

    // ---- layer 2: split gemm/cu pipeline (c2a dead) ----
    gemm_h_kernel<<<gA, 256, GEMM_SMEM>>>((const __half*)p_xc16a, W16 + 2 * D * D,
                                          (float*)p_Z, N_CLI, 0);
    cudaEventRecord(evZ2a, 0);
    gemm_h_kernel<<<gB, 256, GEMM_SMEM>>>((const __half*)p_xc16a, W16 + 2 * D * D,
                                          (float*)p_Z, N_CLI, RSPLIT);
    // s2: cu half A (Y16[0] from s1 L1 chain -> evAgg1; xc16b WAR: reader done before evAgg1)
    cudaStreamWaitEvent(s2, evZ2a, 0);
    cudaStreamWaitEvent(s2, evAgg1, 0);
    client_update_h_kernel<true><<<cuA, 256, 0, s2>>>(
        (const float*)p_Z, b_a2c + 2 * D, Y16b[0], (const int*)p_csr_a2c,
        (const int*)p_off_a2c, (const float*)p_invc_c, (__half*)p_xc16b,
        W_lin, b_lin, out, 0, RSPLIT);
    cudaEventRecord(evCu2a, s2);
    // main: cu half B
    cudaStreamWaitEvent(0, evAgg1, 0);
    client_update_h_kernel<true><<<cuB, 256>>>(
        (const float*)p_Z, b_a2c + 2 * D, Y16b[0], (const int*)p_csr_a2c,
        (const int*)p_off_a2c, (const float*)p_invc_c, (__half*)p_xc16b,
        W_lin, b_lin, out, RSPLIT, N_CLI);
    cudaStreamWaitEvent(0, evCu2a, 0);   // join: all output written before launch returns
}

// round 16
// speedup vs baseline: 1.0558x; 1.0082x over previous
#include <cuda_runtime.h>
#include <cuda_fp16.h>
#include <mma.h>
using namespace nvcuda;

#define N_CLI 100000
#define N_AGG 1000
#define NE    1600000
#define D     128
#define NLAY  3

#define GEMM_SMEM ((64 * 136 + 128 * 136) * 2)   // 52224 B

// ---------------- scratch ----------------
__device__ float  g_xa0[N_AGG * D];
__device__ float  g_xa1[N_AGG * D];
__device__ __half g_Y16[2][N_AGG * D];
__device__ __half g_xc16a[N_CLI * D];
__device__ __half g_xc16b[N_CLI * D];
__device__ __half g_W16[NLAY * D * D];
__device__ float  g_Z[(N_CLI + 128) * D];
__device__ float  g_mean_a[N_AGG * D];
__device__ int    g_csr_c2a[NE];
__device__ int    g_csr_a2c[NE];
__device__ int    g_off_c2a[N_AGG + 1];
__device__ int    g_off_a2c[N_CLI + 1];
__device__ int    g_cur_c2a[N_AGG];
__device__ int    g_cur_a2c[N_CLI];
__device__ int    g_cnt_c2a[N_AGG];
__device__ int    g_cnt_a2c[N_CLI];
__device__ int    g_part[128];
__device__ float  g_invc_a[N_AGG];
__device__ float  g_invc_c[N_CLI];

// ---------------- CSR construction ----------------
__global__ void zero_int_kernel(int* p, int n) {
    int i = blockIdx.x * blockDim.x + threadIdx.x;
    if (i < n) p[i] = 0;
}

__global__ void hist_c2a_kernel(const int* __restrict__ dst, int* __restrict__ cnt) {
    __shared__ int h[N_AGG];
    for (int i = threadIdx.x; i < N_AGG; i += blockDim.x) h[i] = 0;
    __syncthreads();
    for (int e = blockIdx.x * blockDim.x + threadIdx.x; e < NE; e += gridDim.x * blockDim.x)
        atomicAdd(&h[dst[e]], 1);
    __syncthreads();
    for (int i = threadIdx.x; i < N_AGG; i += blockDim.x)
        if (h[i]) atomicAdd(&cnt[i], h[i]);
}

__global__ void hist_a2c_kernel(const int* __restrict__ dst, int* __restrict__ cnt) {
    int e = blockIdx.x * blockDim.x + threadIdx.x;
    if (e < NE) atomicAdd(&cnt[dst[e]], 1);
}

__global__ void scan_init_kernel(const int* __restrict__ cnt, int* __restrict__ off,
                                 int* __restrict__ cur, float* __restrict__ invc, int n) {
    __shared__ int wsum[32];
    __shared__ int carry;
    int tid = threadIdx.x, lane = tid & 31, wid = tid >> 5;
    if (tid == 0) carry = 0;
    __syncthreads();
    for (int base = 0; base < n; base += 1024) {
        int i = base + tid;
        int v = (i < n) ? cnt[i] : 0;
        int x = v;
        #pragma unroll
        for (int o = 1; o < 32; o <<= 1) {
            int t = __shfl_up_sync(0xffffffffu, x, o);
            if (lane >= o) x += t;
        }
        if (lane == 31) wsum[wid] = x;
        __syncthreads();
        if (wid == 0) {
            int s = wsum[lane];
            #pragma unroll
            for (int o = 1; o < 32; o <<= 1) {
                int t = __shfl_up_sync(0xffffffffu, s, o);
                if (lane >= o) s += t;
            }
            wsum[lane] = s;
        }
        __syncthreads();
        int excl = x - v + (wid ? wsum[wid - 1] : 0) + carry;
        if (i < n) {
            off[i] = excl;
            cur[i] = excl;
            invc[i] = 1.0f / fmaxf((float)v, 1.0f);
        }
        __syncthreads();
        if (tid == 0) carry += wsum[31];
        __syncthreads();
    }
    if (threadIdx.x == 0) off[n] = carry;
}

__global__ void scan_blocks_kernel(const int* __restrict__ cnt, int* __restrict__ off,
                                   int* __restrict__ part, int n) {
    __shared__ int wsum[32];
    int tid = threadIdx.x, lane = tid & 31, wid = tid >> 5;
    int i = blockIdx.x * 1024 + tid;
    int v = (i < n) ? cnt[i] : 0;
    int x = v;
    #pragma unroll
    for (int o = 1; o < 32; o <<= 1) {
        int t = __shfl_up_sync(0xffffffffu, x, o);
        if (lane >= o) x += t;
    }
    if (lane == 31) wsum[wid] = x;
    __syncthreads();
    if (wid == 0) {
        int s = wsum[lane];
        #pragma unroll
        for (int o = 1; o < 32; o <<= 1) {
            int t = __shfl_up_sync(0xffffffffu, s, o);
            if (lane >= o) s += t;
        }
        wsum[lane] = s;
    }
    __syncthreads();
    int excl = x - v + (wid ? wsum[wid - 1] : 0);
    if (i < n) off[i] = excl;
    if (tid == 1023) part[blockIdx.x] = excl + v;
}

__global__ void scan_part_kernel(int* part, int nb) {
    if (threadIdx.x == 0) {
        int acc = 0;
        for (int b = 0; b < nb; b++) {
            int v = part[b];
            part[b] = acc;
            acc += v;
        }
        part[nb] = acc;
    }
}

__global__ void scan_add_kernel(const int* __restrict__ cnt, int* __restrict__ off,
                                const int* __restrict__ part, int* __restrict__ cur,
                                float* __restrict__ invc, int n, int nb) {
    int i = blockIdx.x * blockDim.x + threadIdx.x;
    if (i < n) {
        int o = off[i] + part[i >> 10];
        off[i] = o;
        cur[i] = o;
        invc[i] = 1.0f / fmaxf((float)cnt[i], 1.0f);
    }
    if (i == 0) off[n] = part[nb];
}

__global__ void scatter_kernel(const int* __restrict__ src, const int* __restrict__ dst,
                               int* __restrict__ cur, int* __restrict__ csr) {
    int e = blockIdx.x * blockDim.x + threadIdx.x;
    if (e < NE) {
        int p = atomicAdd(&cur[dst[e]], 1);
        csr[p] = src[e];
    }
}

// ---------------- fp32 -> fp16 ----------------
__global__ void f2h_kernel(const float* __restrict__ x, __half* __restrict__ y, int n4) {
    int i = blockIdx.x * blockDim.x + threadIdx.x;
    if (i < n4) {
        float4 v = ((const float4*)x)[i];
        __half2 h0 = __floats2half2_rn(v.x, v.y);
        __half2 h1 = __floats2half2_rn(v.z, v.w);
        float2 pk;
        *(__half2*)&pk.x = h0;
        *(__half2*)&pk.y = h1;
        ((float2*)y)[i] = pk;
    }
}

// ---------------- tiny GEMM: Y16 = xa @ Wl ----------------
__global__ void gemm_small_h_kernel(const float* __restrict__ A, const float* __restrict__ W,
                                    __half* __restrict__ C) {
    __shared__ float row[D];
    int r = blockIdx.x, j = threadIdx.x;
    row[j] = A[r * D + j];
    __syncthreads();
    float acc = 0.f;
    #pragma unroll 8
    for (int k = 0; k < D; k++) acc += row[k] * W[k * D + j];
    C[r * D + j] = __float2half(acc);
}

// xa_new = leaky(mean @ Wl + xa @ Wr + b)
__global__ void agg_update_kernel(const float* __restrict__ mean, const float* __restrict__ xa,
                                  const float* __restrict__ Wl, const float* __restrict__ Wr,
                                  const float* __restrict__ b, float* __restrict__ out) {
    __shared__ float rm[D], rx[D];
    int r = blockIdx.x, j = threadIdx.x;
    rm[j] = mean[r * D + j];
    rx[j] = xa[r * D + j];
    __syncthreads();
    float acc = b[j];
    #pragma unroll 4
    for (int k = 0; k < D; k++) acc += rm[k] * Wl[k * D + j] + rx[k] * Wr[k * D + j];
    out[r * D + j] = (acc >= 0.f) ? acc : 0.1f * acc;
}

// ---------------- c2a aggregation: 512 thr = 8 edge-groups x 64 half2 lanes ----------------
__global__ void __launch_bounds__(512)
agg_c2a_h_kernel(const __half* __restrict__ xc16, const int* __restrict__ csr,
                 const int* __restrict__ off, const float* __restrict__ invc,
                 float* __restrict__ mean) {
    __shared__ float2 part[512];
    int a = blockIdx.x;
    int t = threadIdx.x;
    int c2 = t & 63;
    int g = t >> 6;
    int s = off[a], e = off[a + 1];
    const __half2* X2 = (const __half2*)xc16;
    float2 acc = make_float2(0.f, 0.f);
    int i = s + g;
    for (; i + 8 < e; i += 16) {
        int i0 = csr[i];
        int i1 = csr[i + 8];
        float2 f0 = __half22float2(X2[(size_t)i0 * 64 + c2]);
        float2 f1 = __half22float2(X2[(size_t)i1 * 64 + c2]);
        acc.x += f0.x + f1.x;
        acc.y += f0.y + f1.y;
    }
    if (i < e) {
        float2 f0 = __half22float2(X2[(size_t)csr[i] * 64 + c2]);
        acc.x += f0.x;
        acc.y += f0.y;
    }
    part[t] = acc;
    __syncthreads();
    if (g == 0) {
        float2 m = part[c2];
        #pragma unroll
        for (int k = 1; k < 8; k++) {
            float2 p = part[k * 64 + c2];
            m.x += p.x;
            m.y += p.y;
        }
        float ic = invc[a];
        ((float2*)mean)[a * 64 + c2] = make_float2(m.x * ic, m.y * ic);
    }
}

// ---------------- tensor-core GEMM (validated BM=64 variant) ----------------
__global__ void __launch_bounds__(256, 3)
gemm_h_kernel(const __half* __restrict__ A, const __half* __restrict__ W,
              float* __restrict__ Z, int M) {
    extern __shared__ __half sm[];
    __half* sA = sm;                // [64][136]
    __half* sW = sm + 64 * 136;     // [128][136]
    int tid = threadIdx.x;
    int r0 = blockIdx.x * 64;

    for (int i = tid; i < 64 * 16; i += 256) {
        int row = i >> 4, c8 = (i & 15) * 8;
        int rc = min(r0 + row, M - 1);
        *(float4*)(&sA[row * 136 + c8]) = *(const float4*)(A + (size_t)rc * D + c8);
    }
    for (int i = tid; i < 128 * 16; i += 256) {
        int row = i >> 4, c8 = (i & 15) * 8;
        *(float4*)(&sW[row * 136 + c8]) = *(const float4*)(W + row * D + c8);
    }
    __syncthreads();

    int warp = tid >> 5;
    int wm = warp >> 1;
    int wn = warp & 1;

    wmma::fragment<wmma::accumulator, 16, 16, 16, float> acc[4];
    #pragma unroll
    for (int j = 0; j < 4; j++) wmma::fill_fragment(acc[j], 0.f);

    #pragma unroll
    for (int k = 0; k < 128; k += 16) {
        wmma::fragment<wmma::matrix_a, 16, 16, 16, __half, wmma::row_major> af;
        wmma::load_matrix_sync(af, &sA[(wm * 16) * 136 + k], 136);
        #pragma unroll
        for (int j = 0; j < 4; j++) {
            wmma::fragment<wmma::matrix_b, 16, 16, 16, __half, wmma::row_major> bf;
            wmma::load_matrix_sync(bf, &sW[k * 136 + wn * 64 + j * 16], 136);
            wmma::mma_sync(acc[j], af, bf, acc[j]);
        }
    }

    #pragma unroll
    for (int j = 0; j < 4; j++)
        wmma::store_matrix_sync(&Z[(size_t)(r0 + wm * 16) * D + wn * 64 + j * 16],
                                acc[j], D, wmma::mem_row_major);
}

// ---------------- client update (R8 version, byte-identical) ----------------
template<bool LAST>
__global__ void client_update_h_kernel(const float* __restrict__ Z, const float* __restrict__ bias,
                                       const __half* __restrict__ Y16,
                                       const int* __restrict__ csr, const int* __restrict__ off,
                                       const float* __restrict__ invc,
                                       __half* __restrict__ xc16,
                                       const float* __restrict__ Wlin,
                                       const float* __restrict__ blin,
                                       float* __restrict__ outv) {
    __shared__ float sb[D];
    if (threadIdx.x < D) sb[threadIdx.x] = bias[threadIdx.x];
    __syncthreads();
    int warp = (blockIdx.x * blockDim.x + threadIdx.x) >> 5;
    int lane = threadIdx.x & 31;
    if (warp >= N_CLI) return;
    int s = off[warp], e = off[warp + 1];
    const float2* Y2 = (const float2*)Y16;
    float4 acc = make_float4(0.f, 0.f, 0.f, 0.f);
    for (int base = s; base < e; base += 32) {
        int nv = min(32, e - base);
        int idx = (lane < nv) ? csr[base + lane] : 0;
        for (int t = 0; t < nv; t++) {
            int a = __shfl_sync(0xffffffffu, idx, t);
            float2 raw = Y2[a * 32 + lane];
            __half2 h0 = *(__half2*)&raw.x;
            __half2 h1 = *(__half2*)&raw.y;
            float2 f0 = __half22float2(h0);
            float2 f1 = __half22float2(h1);
            acc.x += f0.x; acc.y += f0.y; acc.z += f1.x; acc.w += f1.y;
        }
    }
    float ic = invc[warp];
    float4 z = ((const float4*)Z)[warp * 32 + lane];
    float4 b4 = *(const float4*)(&sb[lane * 4]);
    float4 v;
    v.x = z.x + b4.x + acc.x * ic;
    v.y = z.y + b4.y + acc.y * ic;
    v.z = z.z + b4.z + acc.z * ic;
    v.w = z.w + b4.w + acc.w * ic;
    v.x = (v.x >= 0.f) ? v.x : 0.1f * v.x;
    v.y = (v.y >= 0.f) ? v.y : 0.1f * v.y;
    v.z = (v.z >= 0.f) ? v.z : 0.1f * v.z;
    v.w = (v.w >= 0.f) ? v.w : 0.1f * v.w;
    if (LAST) {
        float4 w4 = ((const float4*)Wlin)[lane];
        float p = v.x * w4.x + v.y * w4.y + v.z * w4.z + v.w * w4.w;
        #pragma unroll
        for (int o = 16; o; o >>= 1) p += __shfl_xor_sync(0xffffffffu, p, o);
        if (lane == 0) outv[warp] = p + blin[0];
    } else {
        __half2 h0 = __floats2half2_rn(v.x, v.y);
        __half2 h1 = __floats2half2_rn(v.z, v.w);
        float2 pk;
        *(__half2*)&pk.x = h0;
        *(__half2*)&pk.y = h1;
        ((float2*)xc16)[warp * 32 + lane] = pk;
    }
}

// ---------------- launch: triple-stream fork-join ----------------
extern "C" void kernel_launch(void* const* d_in, const int* in_sizes, int n_in,
                              void* d_out, int out_size) {
    (void)in_sizes; (void)n_in; (void)out_size;
    const float* x_clients = (const float*)d_in[0];
    const float* x_agg     = (const float*)d_in[1];
    const int*   c2a_src   = (const int*)d_in[2];
    const int*   c2a_dst   = (const int*)d_in[3];
    const int*   a2c_src   = (const int*)d_in[4];
    const int*   a2c_dst   = (const int*)d_in[5];
    const float* Wl_c2a    = (const float*)d_in[6];
    const float* Wr_c2a    = (const float*)d_in[7];
    const float* b_c2a     = (const float*)d_in[8];
    const float* Wl_a2c    = (const float*)d_in[9];
    const float* Wr_a2c    = (const float*)d_in[10];
    const float* b_a2c     = (const float*)d_in[11];
    const float* W_lin     = (const float*)d_in[12];
    const float* b_lin     = (const float*)d_in[13];
    float* out = (float*)d_out;

    void *p_xa0, *p_xa1, *p_Y16, *p_xc16a, *p_xc16b, *p_W16, *p_Z, *p_mean;
    void *p_csr_c2a, *p_csr_a2c, *p_off_c2a, *p_off_a2c;
    void *p_cur_c2a, *p_cur_a2c, *p_cnt_c2a, *p_cnt_a2c, *p_part, *p_invc_a, *p_invc_c;
    cudaGetSymbolAddress(&p_xa0, g_xa0);
    cudaGetSymbolAddress(&p_xa1, g_xa1);
    cudaGetSymbolAddress(&p_Y16, g_Y16);
    cudaGetSymbolAddress(&p_xc16a, g_xc16a);
    cudaGetSymbolAddress(&p_xc16b, g_xc16b);
    cudaGetSymbolAddress(&p_W16, g_W16);
    cudaGetSymbolAddress(&p_Z, g_Z);
    cudaGetSymbolAddress(&p_mean, g_mean_a);
    cudaGetSymbolAddress(&p_csr_c2a, g_csr_c2a);
    cudaGetSymbolAddress(&p_csr_a2c, g_csr_a2c);
    cudaGetSymbolAddress(&p_off_c2a, g_off_c2a);
    cudaGetSymbolAddress(&p_off_a2c, g_off_a2c);
    cudaGetSymbolAddress(&p_cur_c2a, g_cur_c2a);
    cudaGetSymbolAddress(&p_cur_a2c, g_cur_a2c);
    cudaGetSymbolAddress(&p_cnt_c2a, g_cnt_c2a);
    cudaGetSymbolAddress(&p_cnt_a2c, g_cnt_a2c);
    cudaGetSymbolAddress(&p_part, g_part);
    cudaGetSymbolAddress(&p_invc_a, g_invc_a);
    cudaGetSymbolAddress(&p_invc_c, g_invc_c);

    cudaFuncSetAttribute(gemm_h_kernel, cudaFuncAttributeMaxDynamicSharedMemorySize, GEMM_SMEM);

    static cudaStream_t s1 = nullptr, s2 = nullptr;
    static cudaEvent_t evFork, evPrep, evCsr2, evXcL0, evAgg0, evAgg1;
    if (!s1) {
        cudaStreamCreateWithFlags(&s1, cudaStreamNonBlocking);
        cudaStreamCreateWithFlags(&s2, cudaStreamNonBlocking);
        cudaEventCreateWithFlags(&evFork, cudaEventDisableTiming);
        cudaEventCreateWithFlags(&evPrep, cudaEventDisableTiming);
        cudaEventCreateWithFlags(&evCsr2, cudaEventDisableTiming);
        cudaEventCreateWithFlags(&evXcL0, cudaEventDisableTiming);
        cudaEventCreateWithFlags(&evAgg0, cudaEventDisableTiming);
        cudaEventCreateWithFlags(&evAgg1, cudaEventDisableTiming);
    }

    __half* Y16b[2] = {(__half*)p_Y16, (__half*)p_Y16 + N_AGG * D};
    __half* W16 = (__half*)p_W16;

    int grid_gemm = (N_CLI + 63) / 64;
    int grid_cu = (N_CLI * 32 + 255) / 256;
    int grid_e = (NE + 255) / 256;

    // ---- fork ----
    cudaEventRecord(evFork, 0);
    cudaStreamWaitEvent(s1, evFork, 0);
    cudaStreamWaitEvent(s2, evFork, 0);

    // ---- s1: prep chain (no CSR dependence) ----
    f2h_kernel<<<(NLAY * D * D / 4 + 255) / 256, 256, 0, s1>>>(Wr_a2c, W16, NLAY * D * D / 4);
    f2h_kernel<<<(N_CLI * 32 + 255) / 256, 256, 0, s1>>>(x_clients, (__half*)p_xc16a, N_CLI * 32);
    gemm_small_h_kernel<<<N_AGG, 128, 0, s1>>>(x_agg, Wl_a2c, Y16b[0]);
    gemm_h_kernel<<<grid_gemm, 256, GEMM_SMEM, s1>>>((const __half*)p_xc16a, W16,
                                                     (float*)p_Z, N_CLI);
    cudaEventRecord(evPrep, s1);

    // ---- s2: c2a CSR build (only consumed by s1's agg chains) ----
    zero_int_kernel<<<(N_AGG + 255) / 256, 256, 0, s2>>>((int*)p_cnt_c2a, N_AGG);
    hist_c2a_kernel<<<296, 256, 0, s2>>>(c2a_dst, (int*)p_cnt_c2a);
    scan_init_kernel<<<1, 1024, 0, s2>>>((const int*)p_cnt_c2a, (int*)p_off_c2a,
                                         (int*)p_cur_c2a, (float*)p_invc_a, N_AGG);
    scatter_kernel<<<grid_e, 256, 0, s2>>>(c2a_src, c2a_dst, (int*)p_cur_c2a, (int*)p_csr_c2a);
    cudaEventRecord(evCsr2, s2);

    // ---- main stream: a2c CSR build (cu0's dependency) ----
    zero_int_kernel<<<(N_CLI + 255) / 256, 256>>>((int*)p_cnt_a2c, N_CLI);
    hist_a2c_kernel<<<grid_e, 256>>>(a2c_dst, (int*)p_cnt_a2c);
    int nb = (N_CLI + 1023) / 1024;
    scan_blocks_kernel<<<nb, 1024>>>((const int*)p_cnt_a2c, (int*)p_off_a2c, (int*)p_part, N_CLI);
    scan_part_kernel<<<1, 32>>>((int*)p_part, nb);
    scan_add_kernel<<<(N_CLI + 255) / 256, 256>>>((const int*)p_cnt_a2c, (int*)p_off_a2c,
                                                  (const int*)p_part, (int*)p_cur_a2c,
                                                  (float*)p_invc_c, N_CLI, nb);
    scatter_kernel<<<grid_e, 256>>>(a2c_src, a2c_dst, (int*)p_cur_a2c, (int*)p_csr_a2c);

    // ---- layer 0 ----
    cudaStreamWaitEvent(0, evPrep, 0);
    client_update_h_kernel<false><<<grid_cu, 256>>>(
        (const float*)p_Z, b_a2c, Y16b[0], (const int*)p_csr_a2c,
        (const int*)p_off_a2c, (const float*)p_invc_c, (__half*)p_xc16b,
        W_lin, b_lin, out);
    cudaEventRecord(evXcL0, 0);   // xc16b ready; Y16[0] and Z free

    // s1: L0 c2a chain (needs c2a CSR from s2 + prep's xc16a in-stream)
    cudaStreamWaitEvent(s1, evCsr2, 0);
    agg_c2a_h_kernel<<<N_AGG, 512, 0, s1>>>((const __half*)p_xc16a, (const int*)p_csr_c2a,
                                            (const int*)p_off_c2a, (const float*)p_invc_a,
                                            (float*)p_mean);
    agg_update_kernel<<<N_AGG, 128, 0, s1>>>((const float*)p_mean, x_agg,
                                             Wl_c2a, Wr_c2a, b_c2a, (float*)p_xa0);
    gemm_small_h_kernel<<<N_AGG, 128, 0, s1>>>((const float*)p_xa0, Wl_a2c + 1 * D * D, Y16b[1]);
    cudaEventRecord(evAgg0, s1);   // Y16[1] ready; xc16a's reader (agg_c2a L0) done

    // s1: L1 c2a chain (reads xc16b; writes Y16[0]) -> both gated by evXcL0
    cudaStreamWaitEvent(s1, evXcL0, 0);
    agg_c2a_h_kernel<<<N_AGG, 512, 0, s1>>>((const __half*)p_xc16b, (const int*)p_csr_c2a,
                                            (const int*)p_off_c2a, (const float*)p_invc_a,
                                            (float*)p_mean);
    agg_update_kernel<<<N_AGG, 128, 0, s1>>>((const float*)p_mean, (const float*)p_xa0,
                                             Wl_c2a + 1 * D * D, Wr_c2a + 1 * D * D,
                                             b_c2a + 1 * D, (float*)p_xa1);
    gemm_small_h_kernel<<<N_AGG, 128, 0, s1>>>((const float*)p_xa1, Wl_a2c + 2 * D * D, Y16b[0]);
    cudaEventRecord(evAgg1, s1);   // Y16[0] (layer-2 msg) ready

    // ---- layer 1 (main) ----
    gemm_h_kernel<<<grid_gemm, 256, GEMM_SMEM>>>((const __half*)p_xc16b, W16 + 1 * D * D,
                                                 (float*)p_Z, N_CLI);
    cudaStreamWaitEvent(0, evAgg0, 0);
    client_update_h_kernel<false><<<grid_cu, 256>>>(
        (const float*)p_Z, b_a2c + 1 * D, Y16b[1], (const int*)p_csr_a2c,
        (const int*)p_off_a2c, (const float*)p_invc_c, (__half*)p_xc16a,
        W_lin, b_lin, out);

    // ---- layer 2 (main; c2a dead) ----
    gemm_h_kernel<<<grid_gemm, 256, GEMM_SMEM>>>((const __half*)p_xc16a, W16 + 2 * D * D,
                                                 (float*)p_Z, N_CLI);
    cudaStreamWaitEvent(0, evAgg1, 0);   // Y16[0] from s1's L1 chain
    client_update_h_kernel<true><<<grid_cu, 256>>>(
        (const float*)p_Z, b_a2c + 2 * D, Y16b[0], (const int*)p_csr_a2c,
        (const int*)p_off_a2c, (const float*)p_invc_c, (__half*)p_xc16b,
        W_lin, b_lin, out);
}

// round 17
// speedup vs baseline: 1.0726x; 1.0159x over previous
#include <cuda_runtime.h>
#include <cuda_fp16.h>
#include <mma.h>
using namespace nvcuda;

#define N_CLI 100000
#define N_AGG 1000
#define NE    1600000
#define D     128
#define NLAY  3

#define GEMM_SMEM ((64 * 136 + 128 * 136) * 2)   // 52224 B (>= 64*132*4 epilogue tile)

// ---------------- scratch ----------------
__device__ float  g_xa0[N_AGG * D];
__device__ float  g_xa1[N_AGG * D];
__device__ __half g_Y16[2][N_AGG * D];
__device__ __half g_xc16a[N_CLI * D];
__device__ __half g_xc16b[N_CLI * D];
__device__ __half g_W16[NLAY * D * D];
__device__ __half g_Z16[(N_CLI + 128) * D];
__device__ float  g_mean_a[N_AGG * D];
__device__ int    g_csr_c2a[NE];
__device__ int    g_csr_a2c[NE];
__device__ int    g_off_c2a[N_AGG + 1];
__device__ int    g_off_a2c[N_CLI + 1];
__device__ int    g_cur_c2a[N_AGG];
__device__ int    g_cur_a2c[N_CLI];
__device__ int    g_cnt_c2a[N_AGG];
__device__ int    g_cnt_a2c[N_CLI];
__device__ int    g_part[128];
__device__ float  g_invc_a[N_AGG];
__device__ float  g_invc_c[N_CLI];

// ---------------- CSR construction ----------------
__global__ void zero_int_kernel(int* p, int n) {
    int i = blockIdx.x * blockDim.x + threadIdx.x;
    if (i < n) p[i] = 0;
}

__global__ void hist_c2a_kernel(const int* __restrict__ dst, int* __restrict__ cnt) {
    __shared__ int h[N_AGG];
    for (int i = threadIdx.x; i < N_AGG; i += blockDim.x) h[i] = 0;
    __syncthreads();
    for (int e = blockIdx.x * blockDim.x + threadIdx.x; e < NE; e += gridDim.x * blockDim.x)
        atomicAdd(&h[dst[e]], 1);
    __syncthreads();
    for (int i = threadIdx.x; i < N_AGG; i += blockDim.x)
        if (h[i]) atomicAdd(&cnt[i], h[i]);
}

__global__ void hist_a2c_kernel(const int* __restrict__ dst, int* __restrict__ cnt) {
    int e = blockIdx.x * blockDim.x + threadIdx.x;
    if (e < NE) atomicAdd(&cnt[dst[e]], 1);
}

__global__ void scan_init_kernel(const int* __restrict__ cnt, int* __restrict__ off,
                                 int* __restrict__ cur, float* __restrict__ invc, int n) {
    __shared__ int wsum[32];
    __shared__ int carry;
    int tid = threadIdx.x, lane = tid & 31, wid = tid >> 5;
    if (tid == 0) carry = 0;
    __syncthreads();
    for (int base = 0; base < n; base += 1024) {
        int i = base + tid;
        int v = (i < n) ? cnt[i] : 0;
        int x = v;
        #pragma unroll
        for (int o = 1; o < 32; o <<= 1) {
            int t = __shfl_up_sync(0xffffffffu, x, o);
            if (lane >= o) x += t;
        }
        if (lane == 31) wsum[wid] = x;
        __syncthreads();
        if (wid == 0) {
            int s = wsum[lane];
            #pragma unroll
            for (int o = 1; o < 32; o <<= 1) {
                int t = __shfl_up_sync(0xffffffffu, s, o);
                if (lane >= o) s += t;
            }
            wsum[lane] = s;
        }
        __syncthreads();
        int excl = x - v + (wid ? wsum[wid - 1] : 0) + carry;
        if (i < n) {
            off[i] = excl;
            cur[i] = excl;
            invc[i] = 1.0f / fmaxf((float)v, 1.0f);
        }
        __syncthreads();
        if (tid == 0) carry += wsum[31];
        __syncthreads();
    }
    if (threadIdx.x == 0) off[n] = carry;
}

__global__ void scan_blocks_kernel(const int* __restrict__ cnt, int* __restrict__ off,
                                   int* __restrict__ part, int n) {
    __shared__ int wsum[32];
    int tid = threadIdx.x, lane = tid & 31, wid = tid >> 5;
    int i = blockIdx.x * 1024 + tid;
    int v = (i < n) ? cnt[i] : 0;
    int x = v;
    #pragma unroll
    for (int o = 1; o < 32; o <<= 1) {
        int t = __shfl_up_sync(0xffffffffu, x, o);
        if (lane >= o) x += t;
    }
    if (lane == 31) wsum[wid] = x;
    __syncthreads();
    if (wid == 0) {
        int s = wsum[lane];
        #pragma unroll
        for (int o = 1; o < 32; o <<= 1) {
            int t = __shfl_up_sync(0xffffffffu, s, o);
            if (lane >= o) s += t;
        }
        wsum[lane] = s;
    }
    __syncthreads();
    int excl = x - v + (wid ? wsum[wid - 1] : 0);
    if (i < n) off[i] = excl;
    if (tid == 1023) part[blockIdx.x] = excl + v;
}

__global__ void scan_part_kernel(int* part, int nb) {
    if (threadIdx.x == 0) {
        int acc = 0;
        for (int b = 0; b < nb; b++) {
            int v = part[b];
            part[b] = acc;
            acc += v;
        }
        part[nb] = acc;
    }
}

__global__ void scan_add_kernel(const int* __restrict__ cnt, int* __restrict__ off,
                                const int* __restrict__ part, int* __restrict__ cur,
                                float* __restrict__ invc, int n, int nb) {
    int i = blockIdx.x * blockDim.x + threadIdx.x;
    if (i < n) {
        int o = off[i] + part[i >> 10];
        off[i] = o;
        cur[i] = o;
        invc[i] = 1.0f / fmaxf((float)cnt[i], 1.0f);
    }
    if (i == 0) off[n] = part[nb];
}

__global__ void scatter_kernel(const int* __restrict__ src, const int* __restrict__ dst,
                               int* __restrict__ cur, int* __restrict__ csr) {
    int e = blockIdx.x * blockDim.x + threadIdx.x;
    if (e < NE) {
        int p = atomicAdd(&cur[dst[e]], 1);
        csr[p] = src[e];
    }
}

// ---------------- fp32 -> fp16 ----------------
__global__ void f2h_kernel(const float* __restrict__ x, __half* __restrict__ y, int n4) {
    int i = blockIdx.x * blockDim.x + threadIdx.x;
    if (i < n4) {
        float4 v = ((const float4*)x)[i];
        __half2 h0 = __floats2half2_rn(v.x, v.y);
        __half2 h1 = __floats2half2_rn(v.z, v.w);
        float2 pk;
        *(__half2*)&pk.x = h0;
        *(__half2*)&pk.y = h1;
        ((float2*)y)[i] = pk;
    }
}

// ---------------- tiny GEMM: Y16 = xa @ Wl ----------------
__global__ void gemm_small_h_kernel(const float* __restrict__ A, const float* __restrict__ W,
                                    __half* __restrict__ C) {
    __shared__ float row[D];
    int r = blockIdx.x, j = threadIdx.x;
    row[j] = A[r * D + j];
    __syncthreads();
    float acc = 0.f;
    #pragma unroll 8
    for (int k = 0; k < D; k++) acc += row[k] * W[k * D + j];
    C[r * D + j] = __float2half(acc);
}

// xa_new = leaky(mean @ Wl + xa @ Wr + b)
__global__ void agg_update_kernel(const float* __restrict__ mean, const float* __restrict__ xa,
                                  const float* __restrict__ Wl, const float* __restrict__ Wr,
                                  const float* __restrict__ b, float* __restrict__ out) {
    __shared__ float rm[D], rx[D];
    int r = blockIdx.x, j = threadIdx.x;
    rm[j] = mean[r * D + j];
    rx[j] = xa[r * D + j];
    __syncthreads();
    float acc = b[j];
    #pragma unroll 4
    for (int k = 0; k < D; k++) acc += rm[k] * Wl[k * D + j] + rx[k] * Wr[k * D + j];
    out[r * D + j] = (acc >= 0.f) ? acc : 0.1f * acc;
}

// ---------------- c2a aggregation: 512 thr = 8 edge-groups x 64 half2 lanes ----------------
__global__ void __launch_bounds__(512)
agg_c2a_h_kernel(const __half* __restrict__ xc16, const int* __restrict__ csr,
                 const int* __restrict__ off, const float* __restrict__ invc,
                 float* __restrict__ mean) {
    __shared__ float2 part[512];
    int a = blockIdx.x;
    int t = threadIdx.x;
    int c2 = t & 63;
    int g = t >> 6;
    int s = off[a], e = off[a + 1];
    const __half2* X2 = (const __half2*)xc16;
    float2 acc = make_float2(0.f, 0.f);
    int i = s + g;
    for (; i + 8 < e; i += 16) {
        int i0 = csr[i];
        int i1 = csr[i + 8];
        float2 f0 = __half22float2(X2[(size_t)i0 * 64 + c2]);
        float2 f1 = __half22float2(X2[(size_t)i1 * 64 + c2]);
        acc.x += f0.x + f1.x;
        acc.y += f0.y + f1.y;
    }
    if (i < e) {
        float2 f0 = __half22float2(X2[(size_t)csr[i] * 64 + c2]);
        acc.x += f0.x;
        acc.y += f0.y;
    }
    part[t] = acc;
    __syncthreads();
    if (g == 0) {
        float2 m = part[c2];
        #pragma unroll
        for (int k = 1; k < 8; k++) {
            float2 p = part[k * 64 + c2];
            m.x += p.x;
            m.y += p.y;
        }
        float ic = invc[a];
        ((float2*)mean)[a * 64 + c2] = make_float2(m.x * ic, m.y * ic);
    }
}

// ---------------- tensor-core GEMM: Z16 = A @ W (fp16 output via smem stage) ----------------
__global__ void __launch_bounds__(256, 3)
gemm_h_kernel(const __half* __restrict__ A, const __half* __restrict__ W,
              __half* __restrict__ Z16, int M) {
    extern __shared__ __half sm[];
    __half* sA = sm;                // [64][136]
    __half* sW = sm + 64 * 136;     // [128][136]
    float* tile = (float*)sm;       // epilogue alias: [64][132] fp32 = 33792 B
    int tid = threadIdx.x;
    int r0 = blockIdx.x * 64;

    for (int i = tid; i < 64 * 16; i += 256) {
        int row = i >> 4, c8 = (i & 15) * 8;
        int rc = min(r0 + row, M - 1);
        *(float4*)(&sA[row * 136 + c8]) = *(const float4*)(A + (size_t)rc * D + c8);
    }
    for (int i = tid; i < 128 * 16; i += 256) {
        int row = i >> 4, c8 = (i & 15) * 8;
        *(float4*)(&sW[row * 136 + c8]) = *(const float4*)(W + row * D + c8);
    }
    __syncthreads();

    int warp = tid >> 5;
    int wm = warp >> 1;
    int wn = warp & 1;

    wmma::fragment<wmma::accumulator, 16, 16, 16, float> acc[4];
    #pragma unroll
    for (int j = 0; j < 4; j++) wmma::fill_fragment(acc[j], 0.f);

    #pragma unroll
    for (int k = 0; k < 128; k += 16) {
        wmma::fragment<wmma::matrix_a, 16, 16, 16, __half, wmma::row_major> af;
        wmma::load_matrix_sync(af, &sA[(wm * 16) * 136 + k], 136);
        #pragma unroll
        for (int j = 0; j < 4; j++) {
            wmma::fragment<wmma::matrix_b, 16, 16, 16, __half, wmma::row_major> bf;
            wmma::load_matrix_sync(bf, &sW[k * 136 + wn * 64 + j * 16], 136);
            wmma::mma_sync(acc[j], af, bf, acc[j]);
        }
    }

    __syncthreads();   // all warps done reading sA/sW before tile overwrite
    #pragma unroll
    for (int j = 0; j < 4; j++)
        wmma::store_matrix_sync(&tile[(wm * 16) * 132 + wn * 64 + j * 16],
                                acc[j], 132, wmma::mem_row_major);
    __syncthreads();

    // fp32 tile -> fp16 global (rows padded in g_Z16, write unconditionally)
    for (int i = tid; i < 64 * 64; i += 256) {
        int row = i >> 6, c2 = i & 63;
        float x = tile[row * 132 + c2 * 2];
        float y = tile[row * 132 + c2 * 2 + 1];
        ((__half2*)Z16)[(size_t)(r0 + row) * 64 + c2] = __floats2half2_rn(x, y);
    }
}

// ---------------- client update (R8 gather body; Z now fp16) ----------------
template<bool LAST>
__global__ void client_update_h_kernel(const __half* __restrict__ Z16, const float* __restrict__ bias,
                                       const __half* __restrict__ Y16,
                                       const int* __restrict__ csr, const int* __restrict__ off,
                                       const float* __restrict__ invc,
                                       __half* __restrict__ xc16,
                                       const float* __restrict__ Wlin,
                                       const float* __restrict__ blin,
                                       float* __restrict__ outv) {
    __shared__ float sb[D];
    if (threadIdx.x < D) sb[threadIdx.x] = bias[threadIdx.x];
    __syncthreads();
    int warp = (blockIdx.x * blockDim.x + threadIdx.x) >> 5;
    int lane = threadIdx.x & 31;
    if (warp >= N_CLI) return;
    int s = off[warp], e = off[warp + 1];
    const float2* Y2 = (const float2*)Y16;
    float4 acc = make_float4(0.f, 0.f, 0.f, 0.f);
    for (int base = s; base < e; base += 32) {
        int nv = min(32, e - base);
        int idx = (lane < nv) ? csr[base + lane] : 0;
        for (int t = 0; t < nv; t++) {
            int a = __shfl_sync(0xffffffffu, idx, t);
            float2 raw = Y2[a * 32 + lane];
            __half2 h0 = *(__half2*)&raw.x;
            __half2 h1 = *(__half2*)&raw.y;
            float2 f0 = __half22float2(h0);
            float2 f1 = __half22float2(h1);
            acc.x += f0.x; acc.y += f0.y; acc.z += f1.x; acc.w += f1.y;
        }
    }
    float ic = invc[warp];
    // Z read: 4 halfs per lane (cols lane*4 .. lane*4+3)
    float2 zraw = ((const float2*)Z16)[(size_t)warp * 32 + lane];
    float2 z0 = __half22float2(*(__half2*)&zraw.x);
    float2 z1 = __half22float2(*(__half2*)&zraw.y);
    float4 b4 = *(const float4*)(&sb[lane * 4]);
    float4 v;
    v.x = z0.x + b4.x + acc.x * ic;
    v.y = z0.y + b4.y + acc.y * ic;
    v.z = z1.x + b4.z + acc.z * ic;
    v.w = z1.y + b4.w + acc.w * ic;
    v.x = (v.x >= 0.f) ? v.x : 0.1f * v.x;
    v.y = (v.y >= 0.f) ? v.y : 0.1f * v.y;
    v.z = (v.z >= 0.f) ? v.z : 0.1f * v.z;
    v.w = (v.w >= 0.f) ? v.w : 0.1f * v.w;
    if (LAST) {
        float4 w4 = ((const float4*)Wlin)[lane];
        float p = v.x * w4.x + v.y * w4.y + v.z * w4.z + v.w * w4.w;
        #pragma unroll
        for (int o = 16; o; o >>= 1) p += __shfl_xor_sync(0xffffffffu, p, o);
        if (lane == 0) outv[warp] = p + blin[0];
    } else {
        __half2 h0 = __floats2half2_rn(v.x, v.y);
        __half2 h1 = __floats2half2_rn(v.z, v.w);
        float2 pk;
        *(__half2*)&pk.x = h0;
        *(__half2*)&pk.y = h1;
        ((float2*)xc16)[warp * 32 + lane] = pk;
    }
}

// ---------------- launch: triple-stream fork-join (R13 schedule) ----------------
extern "C" void kernel_launch(void* const* d_in, const int* in_sizes, int n_in,
                              void* d_out, int out_size) {
    (void)in_sizes; (void)n_in; (void)out_size;
    const float* x_clients = (const float*)d_in[0];
    const float* x_agg     = (const float*)d_in[1];
    const int*   c2a_src   = (const int*)d_in[2];
    const int*   c2a_dst   = (const int*)d_in[3];
    const int*   a2c_src   = (const int*)d_in[4];
    const int*   a2c_dst   = (const int*)d_in[5];
    const float* Wl_c2a    = (const float*)d_in[6];
    const float* Wr_c2a    = (const float*)d_in[7];
    const float* b_c2a     = (const float*)d_in[8];
    const float* Wl_a2c    = (const float*)d_in[9];
    const float* Wr_a2c    = (const float*)d_in[10];
    const float* b_a2c     = (const float*)d_in[11];
    const float* W_lin     = (const float*)d_in[12];
    const float* b_lin     = (const float*)d_in[13];
    float* out = (float*)d_out;

    void *p_xa0, *p_xa1, *p_Y16, *p_xc16a, *p_xc16b, *p_W16, *p_Z16, *p_mean;
    void *p_csr_c2a, *p_csr_a2c, *p_off_c2a, *p_off_a2c;
    void *p_cur_c2a, *p_cur_a2c, *p_cnt_c2a, *p_cnt_a2c, *p_part, *p_invc_a, *p_invc_c;
    cudaGetSymbolAddress(&p_xa0, g_xa0);
    cudaGetSymbolAddress(&p_xa1, g_xa1);
    cudaGetSymbolAddress(&p_Y16, g_Y16);
    cudaGetSymbolAddress(&p_xc16a, g_xc16a);
    cudaGetSymbolAddress(&p_xc16b, g_xc16b);
    cudaGetSymbolAddress(&p_W16, g_W16);
    cudaGetSymbolAddress(&p_Z16, g_Z16);
    cudaGetSymbolAddress(&p_mean, g_mean_a);
    cudaGetSymbolAddress(&p_csr_c2a, g_csr_c2a);
    cudaGetSymbolAddress(&p_csr_a2c, g_csr_a2c);
    cudaGetSymbolAddress(&p_off_c2a, g_off_c2a);
    cudaGetSymbolAddress(&p_off_a2c, g_off_a2c);
    cudaGetSymbolAddress(&p_cur_c2a, g_cur_c2a);
    cudaGetSymbolAddress(&p_cur_a2c, g_cur_a2c);
    cudaGetSymbolAddress(&p_cnt_c2a, g_cnt_c2a);
    cudaGetSymbolAddress(&p_cnt_a2c, g_cnt_a2c);
    cudaGetSymbolAddress(&p_part, g_part);
    cudaGetSymbolAddress(&p_invc_a, g_invc_a);
    cudaGetSymbolAddress(&p_invc_c, g_invc_c);

    cudaFuncSetAttribute(gemm_h_kernel, cudaFuncAttributeMaxDynamicSharedMemorySize, GEMM_SMEM);

    static cudaStream_t s1 = nullptr, s2 = nullptr;
    static cudaEvent_t evFork, evPrep, evCsr2, evXcL0, evAgg0, evAgg1;
    if (!s1) {
        cudaStreamCreateWithFlags(&s1, cudaStreamNonBlocking);
        cudaStreamCreateWithFlags(&s2, cudaStreamNonBlocking);
        cudaEventCreateWithFlags(&evFork, cudaEventDisableTiming);
        cudaEventCreateWithFlags(&evPrep, cudaEventDisableTiming);
        cudaEventCreateWithFlags(&evCsr2, cudaEventDisableTiming);
        cudaEventCreateWithFlags(&evXcL0, cudaEventDisableTiming);
        cudaEventCreateWithFlags(&evAgg0, cudaEventDisableTiming);
        cudaEventCreateWithFlags(&evAgg1, cudaEventDisableTiming);
    }

    __half* Y16b[2] = {(__half*)p_Y16, (__half*)p_Y16 + N_AGG * D};
    __half* W16 = (__half*)p_W16;
    __half* Z16 = (__half*)p_Z16;

    int grid_gemm = (N_CLI + 63) / 64;
    int grid_cu = (N_CLI * 32 + 255) / 256;
    int grid_e = (NE + 255) / 256;

    // ---- fork ----
    cudaEventRecord(evFork, 0);
    cudaStreamWaitEvent(s1, evFork, 0);
    cudaStreamWaitEvent(s2, evFork, 0);

    // ---- s1: prep chain (no CSR dependence) ----
    f2h_kernel<<<(NLAY * D * D / 4 + 255) / 256, 256, 0, s1>>>(Wr_a2c, W16, NLAY * D * D / 4);
    f2h_kernel<<<(N_CLI * 32 + 255) / 256, 256, 0, s1>>>(x_clients, (__half*)p_xc16a, N_CLI * 32);
    gemm_small_h_kernel<<<N_AGG, 128, 0, s1>>>(x_agg, Wl_a2c, Y16b[0]);
    gemm_h_kernel<<<grid_gemm, 256, GEMM_SMEM, s1>>>((const __half*)p_xc16a, W16, Z16, N_CLI);
    cudaEventRecord(evPrep, s1);

    // ---- s2: c2a CSR build (only consumed by s1's agg chains) ----
    zero_int_kernel<<<(N_AGG + 255) / 256, 256, 0, s2>>>((int*)p_cnt_c2a, N_AGG);
    hist_c2a_kernel<<<296, 256, 0, s2>>>(c2a_dst, (int*)p_cnt_c2a);
    scan_init_kernel<<<1, 1024, 0, s2>>>((const int*)p_cnt_c2a, (int*)p_off_c2a,
                                         (int*)p_cur_c2a, (float*)p_invc_a, N_AGG);
    scatter_kernel<<<grid_e, 256, 0, s2>>>(c2a_src, c2a_dst, (int*)p_cur_c2a, (int*)p_csr_c2a);
    cudaEventRecord(evCsr2, s2);

    // ---- main stream: a2c CSR build (cu0's dependency) ----
    zero_int_kernel<<<(N_CLI + 255) / 256, 256>>>((int*)p_cnt_a2c, N_CLI);
    hist_a2c_kernel<<<grid_e, 256>>>(a2c_dst, (int*)p_cnt_a2c);
    int nb = (N_CLI + 1023) / 1024;
    scan_blocks_kernel<<<nb, 1024>>>((const int*)p_cnt_a2c, (int*)p_off_a2c, (int*)p_part, N_CLI);
    scan_part_kernel<<<1, 32>>>((int*)p_part, nb);
    scan_add_kernel<<<(N_CLI + 255) / 256, 256>>>((const int*)p_cnt_a2c, (int*)p_off_a2c,
                                                  (const int*)p_part, (int*)p_cur_a2c,
                                                  (float*)p_invc_c, N_CLI, nb);
    scatter_kernel<<<grid_e, 256>>>(a2c_src, a2c_dst, (int*)p_cur_a2c, (int*)p_csr_a2c);

    // ---- layer 0 ----
    cudaStreamWaitEvent(0, evPrep, 0);
    client_update_h_kernel<false><<<grid_cu, 256>>>(
        Z16, b_a2c, Y16b[0], (const int*)p_csr_a2c,
        (const int*)p_off_a2c, (const float*)p_invc_c, (__half*)p_xc16b,
        W_lin, b_lin, out);
    cudaEventRecord(evXcL0, 0);   // xc16b ready; Y16[0] and Z16 free

    // s1: L0 c2a chain (needs c2a CSR from s2 + prep's xc16a in-stream)
    cudaStreamWaitEvent(s1, evCsr2, 0);
    agg_c2a_h_kernel<<<N_AGG, 512, 0, s1>>>((const __half*)p_xc16a, (const int*)p_csr_c2a,
                                            (const int*)p_off_c2a, (const float*)p_invc_a,
                                            (float*)p_mean);
    agg_update_kernel<<<N_AGG, 128, 0, s1>>>((const float*)p_mean, x_agg,
                                             Wl_c2a, Wr_c2a, b_c2a, (float*)p_xa0);
    gemm_small_h_kernel<<<N_AGG, 128, 0, s1>>>((const float*)p_xa0, Wl_a2c + 1 * D * D, Y16b[1]);
    cudaEventRecord(evAgg0, s1);   // Y16[1] ready; xc16a's reader (agg_c2a L0) done

    // s1: L1 c2a chain (reads xc16b; writes Y16[0]) -> both gated by evXcL0
    cudaStreamWaitEvent(s1, evXcL0, 0);
    agg_c2a_h_kernel<<<N_AGG, 512, 0, s1>>>((const __half*)p_xc16b, (const int*)p_csr_c2a,
                                            (const int*)p_off_c2a, (const float*)p_invc_a,
                                            (float*)p_mean);
    agg_update_kernel<<<N_AGG, 128, 0, s1>>>((const float*)p_mean, (const float*)p_xa0,
                                             Wl_c2a + 1 * D * D, Wr_c2a + 1 * D * D,
                                             b_c2a + 1 * D, (float*)p_xa1);
    gemm_small_h_kernel<<<N_AGG, 128, 0, s1>>>((const float*)p_xa1, Wl_a2c + 2 * D * D, Y16b[0]);
    cudaEventRecord(evAgg1, s1);   // Y16[0] (layer-2 msg) ready

    // ---- layer 1 (main) ----
    gemm_h_kernel<<<grid_gemm, 256, GEMM_SMEM>>>((const __half*)p_xc16b, W16 + 1 * D * D,
                                                 Z16, N_CLI);
    cudaStreamWaitEvent(0, evAgg0, 0);
    client_update_h_kernel<false><<<grid_cu, 256>>>(
        Z16, b_a2c + 1 * D, Y16b[1], (const int*)p_csr_a2c,
        (const int*)p_off_a2c, (const float*)p_invc_c, (__half*)p_xc16a,
        W_lin, b_lin, out);

    // ---- layer 2 (main; c2a dead) ----
    gemm_h_kernel<<<grid_gemm, 256, GEMM_SMEM>>>((const __half*)p_xc16a, W16 + 2 * D * D,
                                                 Z16, N_CLI);
    cudaStreamWaitEvent(0, evAgg1, 0);   // Y16[0] from s1's L1 chain
    client_update_h_kernel<true><<<grid_cu, 256>>>(
        Z16, b_a2c + 2 * D, Y16b[0], (const int*)p_csr_a2c,
        (const int*)p_off_a2c, (const float*)p_invc_c, (__half*)p_xc16b,
        W_lin, b_lin, out);
}